// round 8
// baseline (speedup 1.0000x reference)
#include <cuda_runtime.h>
#include <cstdint>

#define NB 4
#define NC 256
#define NH 128
#define NW 128
#define NPIX 16384
#define NHEADS 8
#define NCH 32
#define NSPLIT 32
#define GTILE 64

// ---------------- scratch (static device memory; no allocations) ----------------
__device__ float g_q[NB * NC * NPIX];
__device__ float g_k[NB * NC * NPIX];
__device__ signed char g_vhi[NB * NC * NPIX];
__device__ signed char g_vlo[NB * NC * NPIX];
__device__ signed char g_xhi[NB * NC * NPIX];
__device__ signed char g_xlo[NB * NC * NPIX];
__device__ signed char g_bthi[(size_t)NB * NPIX * 512];  // B^T hi: [b][pix][v 0:256 | x 256:512]
__device__ signed char g_btlo[(size_t)NB * NPIX * 512];
__device__ float g_bscale[NB * 512];                      // per (b, k-row) scale of B
__device__ float g_partial[NSPLIT * NB * NHEADS * NCH * NCH];
__device__ float g_attn[NB * NHEADS * NCH * NCH];
__device__ float g_weff[NC * NC];
__device__ float g_beff[NC];
__device__ signed char g_ahi[NB * NC * 512];
__device__ signed char g_alo[NB * NC * 512];
__device__ float g_ascale[NB * NC];

// ---------------- helpers ----------------
__device__ __forceinline__ uint32_t s2u(const void* p) {
    uint32_t a;
    asm("{ .reg .u64 t; cvta.to.shared.u64 t, %1; cvt.u32.u64 %0, t; }" : "=r"(a) : "l"(p));
    return a;
}
__device__ __forceinline__ void cpa16(uint32_t s, const void* g) {
    asm volatile("cp.async.cg.shared.global [%0], [%1], 16;" :: "r"(s), "l"(g));
}
__device__ __forceinline__ void ldsm4(unsigned& d0, unsigned& d1, unsigned& d2, unsigned& d3,
                                      uint32_t a) {
    asm volatile("ldmatrix.sync.aligned.m8n8.x4.shared.b16 {%0,%1,%2,%3},[%4];"
                 : "=r"(d0), "=r"(d1), "=r"(d2), "=r"(d3) : "r"(a));
}
__device__ __forceinline__ void mma_s8(int* d, const unsigned* a, unsigned b0, unsigned b1) {
    asm volatile(
        "mma.sync.aligned.m16n8k32.row.col.s32.s8.s8.s32 "
        "{%0,%1,%2,%3}, {%4,%5,%6,%7}, {%8,%9}, {%0,%1,%2,%3};"
        : "+r"(d[0]), "+r"(d[1]), "+r"(d[2]), "+r"(d[3])
        : "r"(a[0]), "r"(a[1]), "r"(a[2]), "r"(a[3]), "r"(b0), "r"(b1));
}
__device__ __forceinline__ void quant2(float v, float inv127s, signed char& h, signed char& l) {
    float qs = v * inv127s;             // = 127 * v / s
    float hf = rintf(qs);
    float lf = rintf(254.f * (qs - hf));
    h = (signed char)(int)hf;
    l = (signed char)(int)lf;
}

// ---------------- kernel 1: dwconv 3x3 -> q,k fp32 ; per-plane max; v,x int8 hi/lo ----------------
__global__ __launch_bounds__(256) void dwconv_qkv(
    const float* __restrict__ x,
    const float* __restrict__ qw, const float* __restrict__ qb,
    const float* __restrict__ kw, const float* __restrict__ kb,
    const float* __restrict__ vw, const float* __restrict__ vb)
{
    __shared__ float rv[256], rx[256];

    int bc = blockIdx.x;
    int b  = bc >> 8;
    int c  = bc & (NC - 1);
    const float* xp = x + (size_t)bc * NPIX;
    int tid = threadIdx.x;

    float wq[9], wk[9], wv[9];
#pragma unroll
    for (int t = 0; t < 9; t++) {
        wq[t] = qw[c * 9 + t];
        wk[t] = kw[c * 9 + t];
        wv[t] = vw[c * 9 + t];
    }
    float bq = qb[c], bk = kb[c], bv = vb[c];

    float vmax = 0.f, xmax = 0.f;

    // pass 1: q,k stored; track max|v|, max|x|
    for (int p = tid; p < NPIX / 4; p += 256) {
        int i  = p >> 5;
        int j0 = (p & 31) * 4;
        float l[3][6];
#pragma unroll
        for (int dy = 0; dy < 3; dy++) {
            int ii = i + dy - 1;
            if (ii < 0 || ii >= NH) {
#pragma unroll
                for (int t = 0; t < 6; t++) l[dy][t] = 0.f;
            } else {
                const float* rp = xp + ii * NW;
                l[dy][0] = (j0 > 0) ? __ldg(rp + j0 - 1) : 0.f;
                float4 m = *(const float4*)(rp + j0);
                l[dy][1] = m.x; l[dy][2] = m.y; l[dy][3] = m.z; l[dy][4] = m.w;
                l[dy][5] = (j0 + 4 < NW) ? __ldg(rp + j0 + 4) : 0.f;
            }
        }
        float oq[4], ok[4];
#pragma unroll
        for (int e = 0; e < 4; e++) {
            float aq = bq, ak = bk, av = bv;
#pragma unroll
            for (int dy = 0; dy < 3; dy++)
#pragma unroll
                for (int dx = 0; dx < 3; dx++) {
                    float xv = l[dy][e + dx];
                    int t = dy * 3 + dx;
                    aq = fmaf(wq[t], xv, aq);
                    ak = fmaf(wk[t], xv, ak);
                    av = fmaf(wv[t], xv, av);
                }
            oq[e] = aq; ok[e] = ak;
            vmax = fmaxf(vmax, fabsf(av));
            xmax = fmaxf(xmax, fabsf(l[1][e + 1]));
        }
        size_t o = (size_t)bc * NPIX + (size_t)p * 4;
        *(float4*)(g_q + o) = make_float4(oq[0], oq[1], oq[2], oq[3]);
        *(float4*)(g_k + o) = make_float4(ok[0], ok[1], ok[2], ok[3]);
    }

    rv[tid] = vmax; rx[tid] = xmax;
    __syncthreads();
    for (int s = 128; s; s >>= 1) {
        if (tid < s) {
            rv[tid] = fmaxf(rv[tid], rv[tid + s]);
            rx[tid] = fmaxf(rx[tid], rx[tid + s]);
        }
        __syncthreads();
    }
    float sv = fmaxf(rv[0], 1e-20f);
    float sx = fmaxf(rx[0], 1e-20f);
    if (tid == 0) {
        g_bscale[b * 512 + c]       = sv;
        g_bscale[b * 512 + 256 + c] = sx;
    }
    float iv = 127.f / sv, ix = 127.f / sx;

    // pass 2: recompute v, quantize v and x to int8 hi/lo
    for (int p = tid; p < NPIX / 4; p += 256) {
        int i  = p >> 5;
        int j0 = (p & 31) * 4;
        float l[3][6];
#pragma unroll
        for (int dy = 0; dy < 3; dy++) {
            int ii = i + dy - 1;
            if (ii < 0 || ii >= NH) {
#pragma unroll
                for (int t = 0; t < 6; t++) l[dy][t] = 0.f;
            } else {
                const float* rp = xp + ii * NW;
                l[dy][0] = (j0 > 0) ? __ldg(rp + j0 - 1) : 0.f;
                float4 m = *(const float4*)(rp + j0);
                l[dy][1] = m.x; l[dy][2] = m.y; l[dy][3] = m.z; l[dy][4] = m.w;
                l[dy][5] = (j0 + 4 < NW) ? __ldg(rp + j0 + 4) : 0.f;
            }
        }
        char4 vh, vl, xh, xl;
        signed char* vhp = &vh.x; signed char* vlp = &vl.x;
        signed char* xhp = &xh.x; signed char* xlp = &xl.x;
#pragma unroll
        for (int e = 0; e < 4; e++) {
            float av = bv;
#pragma unroll
            for (int dy = 0; dy < 3; dy++)
#pragma unroll
                for (int dx = 0; dx < 3; dx++)
                    av = fmaf(wv[dy * 3 + dx], l[dy][e + dx], av);
            quant2(av, iv, vhp[e], vlp[e]);
            quant2(l[1][e + 1], ix, xhp[e], xlp[e]);
        }
        size_t o = (size_t)bc * NPIX + (size_t)p * 4;
        *(char4*)(g_vhi + o) = vh;
        *(char4*)(g_vlo + o) = vl;
        *(char4*)(g_xhi + o) = xh;
        *(char4*)(g_xlo + o) = xl;
    }
}

// ---------------- kernel 1b: int8 transpose -> B^T [b][pix][512] ----------------
__global__ __launch_bounds__(256) void transpose_b8()
{
    __shared__ unsigned char ts[64 * 528];

    int b  = blockIdx.x >> 8;
    int n0 = (blockIdx.x & 255) * 64;
    int tid = threadIdx.x;

#pragma unroll
    for (int pass = 0; pass < 2; pass++) {
        const unsigned char* pv = (const unsigned char*)(pass ? g_vlo : g_vhi) + (size_t)b * NC * NPIX;
        const unsigned char* px = (const unsigned char*)(pass ? g_xlo : g_xhi) + (size_t)b * NC * NPIX;
        unsigned char* dst = (unsigned char*)(pass ? g_btlo : g_bthi) + (size_t)b * NPIX * 512;

        if (pass) __syncthreads();

        // gather + 4x4 byte transpose into ts[px][512ch]
#pragma unroll
        for (int i = 0; i < 8; i++) {
            int id = tid + i * 256;
            int srcx = id >> 10;          // 0: v, 1: x
            int rem = id & 1023;
            int cg  = rem >> 4;           // channel group (4 ch)
            int pc  = rem & 15;           // pixel chunk (4 px)
            const unsigned char* sp = srcx ? px : pv;
            unsigned w[4];
#pragma unroll
            for (int cc = 0; cc < 4; cc++)
                w[cc] = *(const unsigned*)(sp + (size_t)(cg * 4 + cc) * NPIX + n0 + pc * 4);
#pragma unroll
            for (int j = 0; j < 4; j++) {
                unsigned o = ((w[0] >> (8 * j)) & 0xffu)
                           | (((w[1] >> (8 * j)) & 0xffu) << 8)
                           | (((w[2] >> (8 * j)) & 0xffu) << 16)
                           | (((w[3] >> (8 * j)) & 0xffu) << 24);
                *(unsigned*)&ts[(pc * 4 + j) * 528 + srcx * 256 + cg * 4] = o;
            }
        }
        __syncthreads();

        // write out rows: 64 px x 512 B
#pragma unroll
        for (int i = 0; i < 8; i++) {
            int id = tid + i * 256;
            int n  = id >> 5;
            int ch = (id & 31) * 16;
            uint4 v = *(const uint4*)&ts[n * 528 + ch];
            *(uint4*)(dst + (size_t)(n0 + n) * 512 + ch) = v;
        }
    }
}

// ---------------- kernel 2: per-(b,h) gram matrix, split over N ----------------
__global__ __launch_bounds__(64) void gram_kernel()
{
    __shared__ __align__(16) float qs[GTILE][36];
    __shared__ __align__(16) float ks[GTILE][36];

    int bh = blockIdx.x;
    int sp = blockIdx.y;
    const int nlen = NPIX / NSPLIT;
    int n0 = sp * nlen;

    const float* qp = g_q + (size_t)bh * NCH * NPIX;
    const float* kp = g_k + (size_t)bh * NCH * NPIX;

    int tid = threadIdx.x;
    int tr = tid >> 3;
    int tc = tid & 7;

    float acc[4][4] = {};

    for (int t0 = n0; t0 < n0 + nlen; t0 += GTILE) {
        for (int l = tid; l < GTILE * NCH; l += 64) {
            int cc = l >> 6;
            int nn = l & 63;
            qs[nn][cc] = qp[(size_t)cc * NPIX + t0 + nn];
            ks[nn][cc] = kp[(size_t)cc * NPIX + t0 + nn];
        }
        __syncthreads();
#pragma unroll 4
        for (int nn = 0; nn < GTILE; nn++) {
            float4 qa = *(const float4*)&qs[nn][tr * 4];
            float4 kb = *(const float4*)&ks[nn][tc * 4];
            float qv[4] = {qa.x, qa.y, qa.z, qa.w};
            float kv[4] = {kb.x, kb.y, kb.z, kb.w};
#pragma unroll
            for (int i = 0; i < 4; i++)
#pragma unroll
                for (int j = 0; j < 4; j++)
                    acc[i][j] = fmaf(qv[i], kv[j], acc[i][j]);
        }
        __syncthreads();
    }

    float* pp = g_partial + ((size_t)sp * NB * NHEADS + bh) * NCH * NCH;
#pragma unroll
    for (int i = 0; i < 4; i++)
#pragma unroll
        for (int j = 0; j < 4; j++)
            pp[(tr * 4 + i) * NCH + (tc * 4 + j)] = acc[i][j];
}

// ---------------- kernel 3: reduce + softmax ----------------
__global__ __launch_bounds__(32) void softmax_kernel(const float* __restrict__ temperature)
{
    int bh = blockIdx.x;
    int h = bh & (NHEADS - 1);
    int c = threadIdx.x;
    float t = temperature[h];

    float vals[NCH];
#pragma unroll
    for (int d = 0; d < NCH; d++) {
        float s = 0.f;
        for (int sp = 0; sp < NSPLIT; sp++)
            s += g_partial[(((size_t)sp * NB * NHEADS + bh) * NCH + c) * NCH + d];
        vals[d] = s * t;
    }
    float mx = vals[0];
#pragma unroll
    for (int d = 1; d < NCH; d++) mx = fmaxf(mx, vals[d]);
    float sum = 0.f;
#pragma unroll
    for (int d = 0; d < NCH; d++) { vals[d] = __expf(vals[d] - mx); sum += vals[d]; }
    float inv = 1.f / sum;
    float* row = g_attn + ((size_t)bh * NCH + c) * NCH;
#pragma unroll
    for (int d = 0; d < NCH; d++) row[d] = vals[d] * inv;
}

// ---------------- kernel P1: W_eff (32x32 tiles) + b_eff ----------------
__global__ __launch_bounds__(256) void weff_kernel(
    const float* __restrict__ fusion_w, const float* __restrict__ out_w,
    const float* __restrict__ out_b, const float* __restrict__ fusion_b,
    const float* __restrict__ gamma)
{
    __shared__ float Fs[32][33];
    __shared__ float Os[32][33];

    int f0 = (blockIdx.x >> 3) * 32;
    int c0 = (blockIdx.x & 7) * 32;
    int tid = threadIdx.x;
    int tx = tid & 15, ty = tid >> 4;

    if ((blockIdx.x & 7) == 0 && tid < 32) {
        int f = f0 + tid;
        float sb = 0.f;
        for (int o = 0; o < NC; o++)
            sb = fmaf(fusion_w[f * 2 * NC + o], out_b[o], sb);
        g_beff[f] = gamma[0] * sb + fusion_b[f];
    }

    float acc[2][2] = {};

    for (int ko = 0; ko < NC; ko += 32) {
#pragma unroll
        for (int r = 0; r < 4; r++) {
            int id = tid + r * 256;
            int ff = id >> 5, kk = id & 31;
            Fs[kk][ff] = fusion_w[(f0 + ff) * (2 * NC) + ko + kk];
            int kk2 = id >> 5, cc = id & 31;
            Os[kk2][cc] = out_w[(ko + kk2) * NC + c0 + cc];
        }
        __syncthreads();
#pragma unroll
        for (int k = 0; k < 32; k++) {
            float fv0 = Fs[k][ty * 2], fv1 = Fs[k][ty * 2 + 1];
            float ov0 = Os[k][tx * 2], ov1 = Os[k][tx * 2 + 1];
            acc[0][0] = fmaf(fv0, ov0, acc[0][0]);
            acc[0][1] = fmaf(fv0, ov1, acc[0][1]);
            acc[1][0] = fmaf(fv1, ov0, acc[1][0]);
            acc[1][1] = fmaf(fv1, ov1, acc[1][1]);
        }
        __syncthreads();
    }
    float g = gamma[0];
#pragma unroll
    for (int i = 0; i < 2; i++)
#pragma unroll
        for (int j = 0; j < 2; j++)
            g_weff[(f0 + ty * 2 + i) * NC + c0 + tx * 2 + j] = g * acc[i][j];
}

// ---------------- kernel P2: A_full -> fold B k-scales, per-row quantize int8 ----------------
__global__ __launch_bounds__(512) void afull_q(const float* __restrict__ fusion_w)
{
    __shared__ float red[512];

    int bf = blockIdx.x;
    int b = bf >> 8, f = bf & 255;
    int col = threadIdx.x;
    float v;
    if (col < NC) {
        int h = col >> 5, d = col & 31;
        const float* wrow = g_weff + f * NC + h * NCH;
        const float* arow = g_attn + ((size_t)(b * NHEADS + h) * NCH) * NCH + d;
        float s = 0.f;
#pragma unroll
        for (int cc = 0; cc < NCH; cc++)
            s = fmaf(wrow[cc], arow[cc * NCH], s);
        v = s;
    } else {
        v = fusion_w[f * 2 * NC + col];
    }
    v *= g_bscale[b * 512 + col];   // fold per-k B scale into A

    red[col] = fabsf(v);
    __syncthreads();
    for (int s = 256; s; s >>= 1) {
        if (col < s) red[col] = fmaxf(red[col], red[col + s]);
        __syncthreads();
    }
    float sm = fmaxf(red[0], 1e-20f);

    signed char hi, lo;
    quant2(v, 127.f / sm, hi, lo);
    size_t o = (size_t)bf * 512 + col;
    g_ahi[o] = hi;
    g_alo[o] = lo;
    if (col == 0) g_ascale[bf] = sm;
}

// ---------------- kernel 4: int8 IMMA main GEMM ----------------
// Y[b](256x16384) = A(256x512) @ B(512x16384) + b_eff via 2-limb int8 (3 products).
// 512 threads = 16 warps (4m x 4n), warp tile 32x32. BM=128, BN=128, BK=64, 4 stages.
#define GP 80                        // smem pitch (bytes) per 64B row: conflict-free ldmatrix
#define PLANE (128 * GP)             // 10240 B
#define STG (4 * PLANE)              // Ahi|Alo|Bhi|Blo = 40960 B per stage
#define GEMM_SMEM (4 * STG)          // 163840 B

__global__ __launch_bounds__(512, 1) void main_gemm_i8(float* __restrict__ y)
{
    extern __shared__ unsigned char sm8[];
    uint32_t sbase = s2u(sm8);

    int tid  = threadIdx.x;
    int lane = tid & 31;
    int warp = tid >> 5;
    int b  = blockIdx.z;
    int m0 = blockIdx.y * 128;
    int n0 = blockIdx.x * 128;
    int wm = (warp >> 2) * 32;
    int wn = (warp & 3) * 32;

    const signed char* gAh = g_ahi + (size_t)(b * NC + m0) * 512;
    const signed char* gAl = g_alo + (size_t)(b * NC + m0) * 512;
    const signed char* gBh = g_bthi + ((size_t)b * NPIX + n0) * 512;
    const signed char* gBl = g_btlo + ((size_t)b * NPIX + n0) * 512;

    int acc1[2][4][4], acc2[2][4][4];
#pragma unroll
    for (int i = 0; i < 2; i++)
#pragma unroll
        for (int j = 0; j < 4; j++)
#pragma unroll
            for (int r = 0; r < 4; r++) { acc1[i][j][r] = 0; acc2[i][j][r] = 0; }

    auto load_stage = [&](int s, int ch) {
        int k0 = ch * 64;
        uint32_t sb = sbase + s * STG;
        // A: 2 limbs x 128 rows x 4 chunks = 1024 -> 2/thread
#pragma unroll
        for (int i = 0; i < 2; i++) {
            int id = tid + i * 512;
            int limb = id >> 9;
            int rem = id & 511;
            int row = rem >> 2;
            int kc  = rem & 3;
            cpa16(sb + limb * PLANE + row * GP + kc * 16,
                  (limb ? gAl : gAh) + (size_t)row * 512 + k0 + kc * 16);
        }
        // B: same shape
#pragma unroll
        for (int i = 0; i < 2; i++) {
            int id = tid + i * 512;
            int limb = id >> 9;
            int rem = id & 511;
            int row = rem >> 2;
            int kc  = rem & 3;
            cpa16(sb + 2 * PLANE + limb * PLANE + row * GP + kc * 16,
                  (limb ? gBl : gBh) + (size_t)row * 512 + k0 + kc * 16);
        }
        asm volatile("cp.async.commit_group;" ::: "memory");
    };

    load_stage(0, 0);
    load_stage(1, 1);
    load_stage(2, 2);

    // ldmatrix lane addressing
    int a_row = wm + (lane & 15);               // + mf*16
    int a_byt = (lane >> 4) * 16;               // + ks*32
    int b_row = wn + ((lane >> 4) & 1) * 8 + (lane & 7);   // + ng*16
    int b_byt = ((lane >> 3) & 1) * 16;         // + ks*32

    for (int it = 0; it < 8; it++) {
        int cur = it & 3;
        asm volatile("cp.async.wait_group 2;" ::: "memory");
        __syncthreads();

        if (it + 3 < 8) load_stage((it + 3) & 3, it + 3);
        else            asm volatile("cp.async.commit_group;" ::: "memory");

        uint32_t sb = sbase + cur * STG;
#pragma unroll
        for (int ks = 0; ks < 2; ks++) {
            int kof = ks * 32;
            unsigned ah[2][4], al[2][4];
#pragma unroll
            for (int mf = 0; mf < 2; mf++) {
                uint32_t ao = sb + (a_row + mf * 16) * GP + kof + a_byt;
                ldsm4(ah[mf][0], ah[mf][1], ah[mf][2], ah[mf][3], ao);
                ldsm4(al[mf][0], al[mf][1], al[mf][2], al[mf][3], ao + PLANE);
            }
            unsigned bh[4][2], bl[4][2];
#pragma unroll
            for (int ng = 0; ng < 2; ng++) {
                uint32_t bo = sb + 2 * PLANE + (b_row + ng * 16) * GP + kof + b_byt;
                unsigned d0, d1, d2, d3;
                ldsm4(d0, d1, d2, d3, bo);
                bh[ng * 2][0] = d0; bh[ng * 2][1] = d1;
                bh[ng * 2 + 1][0] = d2; bh[ng * 2 + 1][1] = d3;
                ldsm4(d0, d1, d2, d3, bo + PLANE);
                bl[ng * 2][0] = d0; bl[ng * 2][1] = d1;
                bl[ng * 2 + 1][0] = d2; bl[ng * 2 + 1][1] = d3;
            }
            // sweep 1: hi*hi -> acc1
#pragma unroll
            for (int nf = 0; nf < 4; nf++)
#pragma unroll
                for (int mf = 0; mf < 2; mf++)
                    mma_s8(acc1[mf][nf], ah[mf], bh[nf][0], bh[nf][1]);
            // sweep 2: hi*lo -> acc2
#pragma unroll
            for (int nf = 0; nf < 4; nf++)
#pragma unroll
                for (int mf = 0; mf < 2; mf++)
                    mma_s8(acc2[mf][nf], ah[mf], bl[nf][0], bl[nf][1]);
            // sweep 3: lo*hi -> acc2
#pragma unroll
            for (int nf = 0; nf < 4; nf++)
#pragma unroll
                for (int mf = 0; mf < 2; mf++)
                    mma_s8(acc2[mf][nf], al[mf], bh[nf][0], bh[nf][1]);
        }
        __syncthreads();
    }

    // epilogue: y = s_m/16129 * (acc1 + acc2/254) + b_eff
    const float I16129 = 1.f / 16129.f;
    const float I254   = 1.f / 254.f;
#pragma unroll
    for (int mf = 0; mf < 2; mf++) {
        int m = m0 + wm + mf * 16 + (lane >> 2);
        float s0 = g_ascale[b * NC + m] * I16129;
        float s1 = g_ascale[b * NC + m + 8] * I16129;
        float be0 = g_beff[m];
        float be1 = g_beff[m + 8];
        float* yr0 = y + (size_t)(b * NC + m) * NPIX + n0 + wn;
        float* yr1 = yr0 + (size_t)8 * NPIX;
#pragma unroll
        for (int nf = 0; nf < 4; nf++) {
            float v0 = s0 * ((float)acc1[mf][nf][0] + (float)acc2[mf][nf][0] * I254) + be0;
            float v1 = s0 * ((float)acc1[mf][nf][1] + (float)acc2[mf][nf][1] * I254) + be0;
            float v2 = s1 * ((float)acc1[mf][nf][2] + (float)acc2[mf][nf][2] * I254) + be1;
            float v3 = s1 * ((float)acc1[mf][nf][3] + (float)acc2[mf][nf][3] * I254) + be1;
            *(float2*)(yr0 + nf * 8 + (lane & 3) * 2) = make_float2(v0, v1);
            *(float2*)(yr1 + nf * 8 + (lane & 3) * 2) = make_float2(v2, v3);
        }
    }
}

// ---------------- launch ----------------
extern "C" void kernel_launch(void* const* d_in, const int* in_sizes, int n_in,
                              void* d_out, int out_size)
{
    const float* x        = (const float*)d_in[0];
    const float* q_w      = (const float*)d_in[1];
    const float* q_b      = (const float*)d_in[2];
    const float* k_w      = (const float*)d_in[3];
    const float* k_b      = (const float*)d_in[4];
    const float* v_w      = (const float*)d_in[5];
    const float* v_b      = (const float*)d_in[6];
    const float* out_w    = (const float*)d_in[7];
    const float* out_b    = (const float*)d_in[8];
    const float* fusion_w = (const float*)d_in[9];
    const float* fusion_b = (const float*)d_in[10];
    const float* temperature = (const float*)d_in[11];
    const float* gamma    = (const float*)d_in[12];
    float* y = (float*)d_out;

    cudaFuncSetAttribute(main_gemm_i8, cudaFuncAttributeMaxDynamicSharedMemorySize, GEMM_SMEM);

    dwconv_qkv<<<NB * NC, 256>>>(x, q_w, q_b, k_w, k_b, v_w, v_b);

    transpose_b8<<<NB * 256, 256>>>();

    dim3 ggrid(NB * NHEADS, NSPLIT);
    gram_kernel<<<ggrid, 64>>>();

    softmax_kernel<<<NB * NHEADS, NCH>>>(temperature);

    weff_kernel<<<64, 256>>>(fusion_w, out_w, out_b, fusion_b, gamma);
    afull_q<<<NB * NC, 512>>>(fusion_w);

    dim3 mgrid(NPIX / 128, NC / 128, NB);
    main_gemm_i8<<<mgrid, 512, GEMM_SMEM>>>(y);
}

// round 9
// speedup vs baseline: 2.4017x; 2.4017x over previous
#include <cuda_runtime.h>
#include <cuda_fp16.h>
#include <cstdint>

#define NB 4
#define NC 256
#define NH 128
#define NW 128
#define NPIX 16384
#define NHEADS 8
#define NCH 32
#define NSPLIT 32
#define GTILE 64

// ---------------- scratch (static device memory; no allocations) ----------------
__device__ float g_q[NB * NC * NPIX];
__device__ float g_k[NB * NC * NPIX];
__device__ __half g_vf[NB * NC * NPIX];       // v as single fp16
__device__ __half g_xf[NB * NC * NPIX];       // x as single fp16
__device__ float g_partial[NSPLIT * NB * NHEADS * NCH * NCH];
__device__ float g_attn[NB * NHEADS * NCH * NCH];
__device__ float g_weff[NC * NC];
__device__ float g_beff[NC];
__device__ __half g_ah[NB * NC * 2 * NC];     // A hi (fp16)
__device__ __half g_al[NB * NC * 2 * NC];     // A lo (fp16)

// ---------------- helpers ----------------
__device__ __forceinline__ void split_f16(float a, __half& hi, __half& lo) {
    hi = __float2half_rn(a);
    lo = __float2half_rn(a - __half2float(hi));
}
__device__ __forceinline__ unsigned pack_h2(__half a, __half b) {
    __half2 t; t.x = a; t.y = b;
    return *(unsigned*)&t;
}
__device__ __forceinline__ void mma_f16(float* d, const unsigned* a, const unsigned* b) {
    asm volatile(
        "mma.sync.aligned.m16n8k16.row.col.f32.f16.f16.f32 "
        "{%0,%1,%2,%3}, {%4,%5,%6,%7}, {%8,%9}, {%0,%1,%2,%3};"
        : "+f"(d[0]), "+f"(d[1]), "+f"(d[2]), "+f"(d[3])
        : "r"(a[0]), "r"(a[1]), "r"(a[2]), "r"(a[3]), "r"(b[0]), "r"(b[1]));
}
__device__ __forceinline__ void ldsm4(unsigned& d0, unsigned& d1, unsigned& d2, unsigned& d3,
                                      const void* p) {
    unsigned a = (unsigned)__cvta_generic_to_shared(p);
    asm volatile("ldmatrix.sync.aligned.m8n8.x4.shared.b16 {%0,%1,%2,%3},[%4];"
                 : "=r"(d0), "=r"(d1), "=r"(d2), "=r"(d3) : "r"(a));
}
__device__ __forceinline__ void ldsm4t(unsigned& d0, unsigned& d1, unsigned& d2, unsigned& d3,
                                       const void* p) {
    unsigned a = (unsigned)__cvta_generic_to_shared(p);
    asm volatile("ldmatrix.sync.aligned.m8n8.x4.trans.shared.b16 {%0,%1,%2,%3},[%4];"
                 : "=r"(d0), "=r"(d1), "=r"(d2), "=r"(d3) : "r"(a));
}
__device__ __forceinline__ void cpa16(void* s, const void* g) {
    unsigned sa = (unsigned)__cvta_generic_to_shared(s);
    asm volatile("cp.async.cg.shared.global [%0], [%1], 16;" :: "r"(sa), "l"(g));
}

// ---------------- kernel 1: dwconv 3x3 -> q,k fp32 ; v,x single fp16 ----------------
__global__ __launch_bounds__(256) void dwconv_qkv(
    const float* __restrict__ x,
    const float* __restrict__ qw, const float* __restrict__ qb,
    const float* __restrict__ kw, const float* __restrict__ kb,
    const float* __restrict__ vw, const float* __restrict__ vb)
{
    int bc = blockIdx.x;
    int c  = bc & (NC - 1);
    const float* xp = x + (size_t)bc * NPIX;

    float wq[9], wk[9], wv[9];
#pragma unroll
    for (int t = 0; t < 9; t++) {
        wq[t] = qw[c * 9 + t];
        wk[t] = kw[c * 9 + t];
        wv[t] = vw[c * 9 + t];
    }
    float bq = qb[c], bk = kb[c], bv = vb[c];

    for (int p = threadIdx.x; p < NPIX / 4; p += 256) {
        int i  = p >> 5;
        int j0 = (p & 31) * 4;
        float l[3][6];
#pragma unroll
        for (int dy = 0; dy < 3; dy++) {
            int ii = i + dy - 1;
            if (ii < 0 || ii >= NH) {
#pragma unroll
                for (int t = 0; t < 6; t++) l[dy][t] = 0.f;
            } else {
                const float* rp = xp + ii * NW;
                l[dy][0] = (j0 > 0) ? __ldg(rp + j0 - 1) : 0.f;
                float4 m = *(const float4*)(rp + j0);
                l[dy][1] = m.x; l[dy][2] = m.y; l[dy][3] = m.z; l[dy][4] = m.w;
                l[dy][5] = (j0 + 4 < NW) ? __ldg(rp + j0 + 4) : 0.f;
            }
        }
        float oq[4], ok[4], ov[4];
#pragma unroll
        for (int e = 0; e < 4; e++) {
            float aq = bq, ak = bk, av = bv;
#pragma unroll
            for (int dy = 0; dy < 3; dy++)
#pragma unroll
                for (int dx = 0; dx < 3; dx++) {
                    float xv = l[dy][e + dx];
                    int t = dy * 3 + dx;
                    aq = fmaf(wq[t], xv, aq);
                    ak = fmaf(wk[t], xv, ak);
                    av = fmaf(wv[t], xv, av);
                }
            oq[e] = aq; ok[e] = ak; ov[e] = av;
        }
        size_t o = (size_t)bc * NPIX + (size_t)p * 4;
        *(float4*)(g_q + o) = make_float4(oq[0], oq[1], oq[2], oq[3]);
        *(float4*)(g_k + o) = make_float4(ok[0], ok[1], ok[2], ok[3]);

        *(uint2*)(g_vf + o) = make_uint2(
            pack_h2(__float2half_rn(ov[0]), __float2half_rn(ov[1])),
            pack_h2(__float2half_rn(ov[2]), __float2half_rn(ov[3])));
        *(uint2*)(g_xf + o) = make_uint2(
            pack_h2(__float2half_rn(l[1][1]), __float2half_rn(l[1][2])),
            pack_h2(__float2half_rn(l[1][3]), __float2half_rn(l[1][4])));
    }
}

// ---------------- kernel 2: per-(b,h) gram matrix, split over N ----------------
__global__ __launch_bounds__(64) void gram_kernel()
{
    __shared__ __align__(16) float qs[GTILE][36];
    __shared__ __align__(16) float ks[GTILE][36];

    int bh = blockIdx.x;
    int sp = blockIdx.y;
    const int nlen = NPIX / NSPLIT;
    int n0 = sp * nlen;

    const float* qp = g_q + (size_t)bh * NCH * NPIX;
    const float* kp = g_k + (size_t)bh * NCH * NPIX;

    int tid = threadIdx.x;
    int tr = tid >> 3;
    int tc = tid & 7;

    float acc[4][4] = {};

    for (int t0 = n0; t0 < n0 + nlen; t0 += GTILE) {
        for (int l = tid; l < GTILE * NCH; l += 64) {
            int cc = l >> 6;
            int nn = l & 63;
            qs[nn][cc] = qp[(size_t)cc * NPIX + t0 + nn];
            ks[nn][cc] = kp[(size_t)cc * NPIX + t0 + nn];
        }
        __syncthreads();
#pragma unroll 4
        for (int nn = 0; nn < GTILE; nn++) {
            float4 qa = *(const float4*)&qs[nn][tr * 4];
            float4 kb = *(const float4*)&ks[nn][tc * 4];
            float qv[4] = {qa.x, qa.y, qa.z, qa.w};
            float kv[4] = {kb.x, kb.y, kb.z, kb.w};
#pragma unroll
            for (int i = 0; i < 4; i++)
#pragma unroll
                for (int j = 0; j < 4; j++)
                    acc[i][j] = fmaf(qv[i], kv[j], acc[i][j]);
        }
        __syncthreads();
    }

    float* pp = g_partial + ((size_t)sp * NB * NHEADS + bh) * NCH * NCH;
#pragma unroll
    for (int i = 0; i < 4; i++)
#pragma unroll
        for (int j = 0; j < 4; j++)
            pp[(tr * 4 + i) * NCH + (tc * 4 + j)] = acc[i][j];
}

// ---------------- kernel 3: parallel reduce + softmax (256 thr / bh) ----------------
__global__ __launch_bounds__(256) void softmax_kernel(const float* __restrict__ temperature)
{
    __shared__ float sv[NCH * NCH];   // 1024

    int bh = blockIdx.x;
    int h = bh & (NHEADS - 1);
    int tid = threadIdx.x;
    int lane = tid & 31;
    int warp = tid >> 5;

    // reduce 32 partials; each thread owns 4 consecutive entries (float4)
    float4 acc = make_float4(0.f, 0.f, 0.f, 0.f);
#pragma unroll 8
    for (int sp = 0; sp < NSPLIT; sp++) {
        const float* p = g_partial + ((size_t)sp * NB * NHEADS + bh) * (NCH * NCH) + tid * 4;
        float4 v = *(const float4*)p;
        acc.x += v.x; acc.y += v.y; acc.z += v.z; acc.w += v.w;
    }
    *(float4*)&sv[tid * 4] = acc;
    __syncthreads();

    // softmax: warp w handles rows 4w..4w+3 (row = c, 32 cols)
    float t = temperature[h];
#pragma unroll
    for (int r = 0; r < 4; r++) {
        int row = warp * 4 + r;
        float v = sv[row * NCH + lane] * t;
        float mx = v;
#pragma unroll
        for (int o = 16; o; o >>= 1) mx = fmaxf(mx, __shfl_xor_sync(0xffffffffu, mx, o));
        float e = __expf(v - mx);
        float s = e;
#pragma unroll
        for (int o = 16; o; o >>= 1) s += __shfl_xor_sync(0xffffffffu, s, o);
        g_attn[(size_t)bh * (NCH * NCH) + row * NCH + lane] = e / s;
    }
}

// ---------------- kernel P1: W_eff (32x32 tiles) + b_eff ----------------
__global__ __launch_bounds__(256) void weff_kernel(
    const float* __restrict__ fusion_w, const float* __restrict__ out_w,
    const float* __restrict__ out_b, const float* __restrict__ fusion_b,
    const float* __restrict__ gamma)
{
    __shared__ float Fs[32][33];
    __shared__ float Os[32][33];

    int f0 = (blockIdx.x >> 3) * 32;
    int c0 = (blockIdx.x & 7) * 32;
    int tid = threadIdx.x;
    int tx = tid & 15, ty = tid >> 4;

    if ((blockIdx.x & 7) == 0 && tid < 32) {
        int f = f0 + tid;
        float sb = 0.f;
        for (int o = 0; o < NC; o++)
            sb = fmaf(fusion_w[f * 2 * NC + o], out_b[o], sb);
        g_beff[f] = gamma[0] * sb + fusion_b[f];
    }

    float acc[2][2] = {};

    for (int ko = 0; ko < NC; ko += 32) {
#pragma unroll
        for (int r = 0; r < 4; r++) {
            int id = tid + r * 256;
            int ff = id >> 5, kk = id & 31;
            Fs[kk][ff] = fusion_w[(f0 + ff) * (2 * NC) + ko + kk];
            int kk2 = id >> 5, cc = id & 31;
            Os[kk2][cc] = out_w[(ko + kk2) * NC + c0 + cc];
        }
        __syncthreads();
#pragma unroll
        for (int k = 0; k < 32; k++) {
            float fv0 = Fs[k][ty * 2], fv1 = Fs[k][ty * 2 + 1];
            float ov0 = Os[k][tx * 2], ov1 = Os[k][tx * 2 + 1];
            acc[0][0] = fmaf(fv0, ov0, acc[0][0]);
            acc[0][1] = fmaf(fv0, ov1, acc[0][1]);
            acc[1][0] = fmaf(fv1, ov0, acc[1][0]);
            acc[1][1] = fmaf(fv1, ov1, acc[1][1]);
        }
        __syncthreads();
    }
    float g = gamma[0];
#pragma unroll
    for (int i = 0; i < 2; i++)
#pragma unroll
        for (int j = 0; j < 2; j++)
            g_weff[(f0 + ty * 2 + i) * NC + c0 + tx * 2 + j] = g * acc[i][j];
}

// ---------------- kernel P2: A_full -> fp16 hi/lo ----------------
__global__ __launch_bounds__(512) void afull_kernel(const float* __restrict__ fusion_w)
{
    int bf = blockIdx.x;
    int b = bf >> 8, f = bf & 255;
    int col = threadIdx.x;
    float v;
    if (col < NC) {
        int h = col >> 5, d = col & 31;
        const float* wrow = g_weff + f * NC + h * NCH;
        const float* arow = g_attn + ((size_t)(b * NHEADS + h) * NCH) * NCH + d;
        float s = 0.f;
#pragma unroll
        for (int cc = 0; cc < NCH; cc++)
            s = fmaf(wrow[cc], arow[cc * NCH], s);
        v = s;
    } else {
        v = fusion_w[f * 2 * NC + col];
    }
    __half hi, lo;
    split_f16(v, hi, lo);
    g_ah[(size_t)bf * 2 * NC + col] = hi;
    g_al[(size_t)bf * 2 * NC + col] = lo;
}

// ---------------- kernel 4: main GEMM — fp16 HMMA 2-product, cp.async 2-stage, BK=32 ----------------
// Y[b](256x16384) = (Ah+Al)(256x512) @ Bh(512x16384) + b_eff
// BM=128, BN=128, BK=32, 256 threads = 8 warps (2m x 4n), warp tile 64x32.
#define AP 40     // A smem pitch: 80B rows -> conflict-free ldmatrix
#define BP 136    // B smem pitch: 272B rows -> conflict-free ldmatrix.trans
__global__ __launch_bounds__(256, 2) void main_gemm(float* __restrict__ y)
{
    __shared__ __align__(128) __half As[2][2][128][AP];   // [stage][hi/lo][m][k]
    __shared__ __align__(128) __half Bs[2][32][BP];       // [stage][k][n]

    int b  = blockIdx.z;
    int m0 = blockIdx.y * 128;
    int n0 = blockIdx.x * 128;
    int tid  = threadIdx.x;
    int lane = tid & 31;
    int warp = tid >> 5;
    int wm = (warp >> 2) * 64;
    int wn = (warp & 3) * 32;
    int g = lane >> 2;
    int t = lane & 3;

    int lr = lane & 15;          // ldmatrix row within 16
    int lc = (lane >> 4) * 8;    // ldmatrix 8-col group

    const __half* gA[2] = { g_ah + (size_t)(b * NC + m0) * (2 * NC),
                            g_al + (size_t)(b * NC + m0) * (2 * NC) };

    float acc[4][4][4];
#pragma unroll
    for (int i = 0; i < 4; i++)
#pragma unroll
        for (int j = 0; j < 4; j++)
#pragma unroll
            for (int r = 0; r < 4; r++) acc[i][j][r] = 0.f;

    auto load_stage = [&](int s, int it) {
        int k0 = it * 32;
        // A: 2 planes x 128 rows x 32 k = 1024 chunks(16B), 4/thread
#pragma unroll
        for (int c = 0; c < 4; c++) {
            int id = tid + c * 256;
            int half_ = id >> 9;
            int rem = id & 511;
            int row = rem >> 2;
            int kc = (rem & 3) * 8;
            cpa16(&As[s][half_][row][kc], gA[half_] + (size_t)row * (2 * NC) + k0 + kc);
        }
        // B: 32 k x 128 n = 512 chunks, 2/thread
#pragma unroll
        for (int c = 0; c < 2; c++) {
            int id = tid + c * 256;
            int krow = id >> 4;
            int nc = (id & 15) * 8;
            int grow = k0 + krow;
            const __half* src = (grow < NC)
                ? g_vf + (size_t)(b * NC + grow) * NPIX + n0 + nc
                : g_xf + (size_t)(b * NC + grow - NC) * NPIX + n0 + nc;
            cpa16(&Bs[s][krow][nc], src);
        }
        asm volatile("cp.async.commit_group;");
    };

    load_stage(0, 0);

    const int NIT = (2 * NC) / 32;   // 16
    for (int it = 0; it < NIT; it++) {
        int cur = it & 1;
        if (it + 1 < NIT) {
            load_stage(cur ^ 1, it + 1);
            asm volatile("cp.async.wait_group 1;");
        } else {
            asm volatile("cp.async.wait_group 0;");
        }
        __syncthreads();

#pragma unroll
        for (int ks = 0; ks < 2; ks++) {
            int kof = ks * 16;
            // B fragments
            unsigned bh[4][2];
#pragma unroll
            for (int nb = 0; nb < 2; nb++) {
                unsigned d0, d1, d2, d3;
                ldsm4t(d0, d1, d2, d3, &Bs[cur][kof + lr][wn + nb * 16 + lc]);
                bh[nb * 2][0] = d0; bh[nb * 2][1] = d1;
                bh[nb * 2 + 1][0] = d2; bh[nb * 2 + 1][1] = d3;
            }
            // A-hi fragments + sweep 1
            unsigned af[4][4];
#pragma unroll
            for (int mf = 0; mf < 4; mf++)
                ldsm4(af[mf][0], af[mf][1], af[mf][2], af[mf][3],
                      &As[cur][0][wm + mf * 16 + lr][kof + lc]);
#pragma unroll
            for (int nf = 0; nf < 4; nf++)
#pragma unroll
                for (int mf = 0; mf < 4; mf++)
                    mma_f16(acc[mf][nf], af[mf], bh[nf]);
            // A-lo fragments + sweep 2
#pragma unroll
            for (int mf = 0; mf < 4; mf++)
                ldsm4(af[mf][0], af[mf][1], af[mf][2], af[mf][3],
                      &As[cur][1][wm + mf * 16 + lr][kof + lc]);
#pragma unroll
            for (int nf = 0; nf < 4; nf++)
#pragma unroll
                for (int mf = 0; mf < 4; mf++)
                    mma_f16(acc[mf][nf], af[mf], bh[nf]);
        }
        __syncthreads();
    }

    // epilogue
#pragma unroll
    for (int mf = 0; mf < 4; mf++) {
        int m = m0 + wm + mf * 16 + g;
        float be0 = g_beff[m];
        float be1 = g_beff[m + 8];
        float* yr0 = y + (size_t)(b * NC + m) * NPIX + n0 + wn;
        float* yr1 = yr0 + (size_t)8 * NPIX;
#pragma unroll
        for (int nf = 0; nf < 4; nf++) {
            *(float2*)(yr0 + nf * 8 + t * 2) =
                make_float2(acc[mf][nf][0] + be0, acc[mf][nf][1] + be0);
            *(float2*)(yr1 + nf * 8 + t * 2) =
                make_float2(acc[mf][nf][2] + be1, acc[mf][nf][3] + be1);
        }
    }
}

// ---------------- launch ----------------
extern "C" void kernel_launch(void* const* d_in, const int* in_sizes, int n_in,
                              void* d_out, int out_size)
{
    const float* x        = (const float*)d_in[0];
    const float* q_w      = (const float*)d_in[1];
    const float* q_b      = (const float*)d_in[2];
    const float* k_w      = (const float*)d_in[3];
    const float* k_b      = (const float*)d_in[4];
    const float* v_w      = (const float*)d_in[5];
    const float* v_b      = (const float*)d_in[6];
    const float* out_w    = (const float*)d_in[7];
    const float* out_b    = (const float*)d_in[8];
    const float* fusion_w = (const float*)d_in[9];
    const float* fusion_b = (const float*)d_in[10];
    const float* temperature = (const float*)d_in[11];
    const float* gamma    = (const float*)d_in[12];
    float* y = (float*)d_out;

    dwconv_qkv<<<NB * NC, 256>>>(x, q_w, q_b, k_w, k_b, v_w, v_b);

    dim3 ggrid(NB * NHEADS, NSPLIT);
    gram_kernel<<<ggrid, 64>>>();

    softmax_kernel<<<NB * NHEADS, 256>>>(temperature);

    weff_kernel<<<64, 256>>>(fusion_w, out_w, out_b, fusion_b, gamma);
    afull_kernel<<<NB * NC, 2 * NC>>>(fusion_w);

    dim3 mgrid(NPIX / 128, NC / 128, NB);
    main_gemm<<<mgrid, 256>>>(y);
}

// round 10
// speedup vs baseline: 2.8725x; 1.1960x over previous
#include <cuda_runtime.h>
#include <cuda_fp16.h>
#include <cstdint>

#define NB 4
#define NC 256
#define NH 128
#define NW 128
#define NPIX 16384
#define NHEADS 8
#define NCH 32
#define NSPLIT 32
#define GTILE 64

// ---------------- scratch (static device memory; no allocations) ----------------
__device__ float g_q[NB * NC * NPIX];
__device__ float g_k[NB * NC * NPIX];
__device__ __half g_vf[NB * NC * NPIX];       // v as fp16
__device__ __half g_xf[NB * NC * NPIX];       // x as fp16
__device__ float g_partial[NSPLIT * NB * NHEADS * NCH * NCH];
__device__ float g_attn[NB * NHEADS * NCH * NCH];
__device__ float g_weff[NC * NC];
__device__ float g_beff[NC];
__device__ __half g_af[NB * NC * 2 * NC];     // A as fp16

// ---------------- helpers ----------------
__device__ __forceinline__ unsigned pack_h2(__half a, __half b) {
    __half2 t; t.x = a; t.y = b;
    return *(unsigned*)&t;
}
__device__ __forceinline__ void mma_f16(float* d, const unsigned* a, const unsigned* b) {
    asm volatile(
        "mma.sync.aligned.m16n8k16.row.col.f32.f16.f16.f32 "
        "{%0,%1,%2,%3}, {%4,%5,%6,%7}, {%8,%9}, {%0,%1,%2,%3};"
        : "+f"(d[0]), "+f"(d[1]), "+f"(d[2]), "+f"(d[3])
        : "r"(a[0]), "r"(a[1]), "r"(a[2]), "r"(a[3]), "r"(b[0]), "r"(b[1]));
}
__device__ __forceinline__ void ldsm4(unsigned& d0, unsigned& d1, unsigned& d2, unsigned& d3,
                                      const void* p) {
    unsigned a = (unsigned)__cvta_generic_to_shared(p);
    asm volatile("ldmatrix.sync.aligned.m8n8.x4.shared.b16 {%0,%1,%2,%3},[%4];"
                 : "=r"(d0), "=r"(d1), "=r"(d2), "=r"(d3) : "r"(a));
}
__device__ __forceinline__ void ldsm4t(unsigned& d0, unsigned& d1, unsigned& d2, unsigned& d3,
                                       const void* p) {
    unsigned a = (unsigned)__cvta_generic_to_shared(p);
    asm volatile("ldmatrix.sync.aligned.m8n8.x4.trans.shared.b16 {%0,%1,%2,%3},[%4];"
                 : "=r"(d0), "=r"(d1), "=r"(d2), "=r"(d3) : "r"(a));
}
__device__ __forceinline__ void cpa16(void* s, const void* g) {
    unsigned sa = (unsigned)__cvta_generic_to_shared(s);
    asm volatile("cp.async.cg.shared.global [%0], [%1], 16;" :: "r"(sa), "l"(g));
}

// ---------------- kernel 1: dwconv 3x3 -> q,k fp32 ; v,x fp16 ----------------
__global__ __launch_bounds__(256) void dwconv_qkv(
    const float* __restrict__ x,
    const float* __restrict__ qw, const float* __restrict__ qb,
    const float* __restrict__ kw, const float* __restrict__ kb,
    const float* __restrict__ vw, const float* __restrict__ vb)
{
    int bc = blockIdx.x;
    int c  = bc & (NC - 1);
    const float* xp = x + (size_t)bc * NPIX;

    float wq[9], wk[9], wv[9];
#pragma unroll
    for (int t = 0; t < 9; t++) {
        wq[t] = qw[c * 9 + t];
        wk[t] = kw[c * 9 + t];
        wv[t] = vw[c * 9 + t];
    }
    float bq = qb[c], bk = kb[c], bv = vb[c];

    for (int p = threadIdx.x; p < NPIX / 4; p += 256) {
        int i  = p >> 5;
        int j0 = (p & 31) * 4;
        float l[3][6];
#pragma unroll
        for (int dy = 0; dy < 3; dy++) {
            int ii = i + dy - 1;
            if (ii < 0 || ii >= NH) {
#pragma unroll
                for (int t = 0; t < 6; t++) l[dy][t] = 0.f;
            } else {
                const float* rp = xp + ii * NW;
                l[dy][0] = (j0 > 0) ? __ldg(rp + j0 - 1) : 0.f;
                float4 m = *(const float4*)(rp + j0);
                l[dy][1] = m.x; l[dy][2] = m.y; l[dy][3] = m.z; l[dy][4] = m.w;
                l[dy][5] = (j0 + 4 < NW) ? __ldg(rp + j0 + 4) : 0.f;
            }
        }
        float oq[4], ok[4], ov[4];
#pragma unroll
        for (int e = 0; e < 4; e++) {
            float aq = bq, ak = bk, av = bv;
#pragma unroll
            for (int dy = 0; dy < 3; dy++)
#pragma unroll
                for (int dx = 0; dx < 3; dx++) {
                    float xv = l[dy][e + dx];
                    int t = dy * 3 + dx;
                    aq = fmaf(wq[t], xv, aq);
                    ak = fmaf(wk[t], xv, ak);
                    av = fmaf(wv[t], xv, av);
                }
            oq[e] = aq; ok[e] = ak; ov[e] = av;
        }
        size_t o = (size_t)bc * NPIX + (size_t)p * 4;
        *(float4*)(g_q + o) = make_float4(oq[0], oq[1], oq[2], oq[3]);
        *(float4*)(g_k + o) = make_float4(ok[0], ok[1], ok[2], ok[3]);

        *(uint2*)(g_vf + o) = make_uint2(
            pack_h2(__float2half_rn(ov[0]), __float2half_rn(ov[1])),
            pack_h2(__float2half_rn(ov[2]), __float2half_rn(ov[3])));
        *(uint2*)(g_xf + o) = make_uint2(
            pack_h2(__float2half_rn(l[1][1]), __float2half_rn(l[1][2])),
            pack_h2(__float2half_rn(l[1][3]), __float2half_rn(l[1][4])));
    }
}

// ---------------- kernel 2: per-(b,h) gram matrix, split over N ----------------
__global__ __launch_bounds__(64) void gram_kernel()
{
    __shared__ __align__(16) float qs[GTILE][36];
    __shared__ __align__(16) float ks[GTILE][36];

    int bh = blockIdx.x;
    int sp = blockIdx.y;
    const int nlen = NPIX / NSPLIT;
    int n0 = sp * nlen;

    const float* qp = g_q + (size_t)bh * NCH * NPIX;
    const float* kp = g_k + (size_t)bh * NCH * NPIX;

    int tid = threadIdx.x;
    int tr = tid >> 3;
    int tc = tid & 7;

    float acc[4][4] = {};

    for (int t0 = n0; t0 < n0 + nlen; t0 += GTILE) {
        for (int l = tid; l < GTILE * NCH; l += 64) {
            int cc = l >> 6;
            int nn = l & 63;
            qs[nn][cc] = qp[(size_t)cc * NPIX + t0 + nn];
            ks[nn][cc] = kp[(size_t)cc * NPIX + t0 + nn];
        }
        __syncthreads();
#pragma unroll 4
        for (int nn = 0; nn < GTILE; nn++) {
            float4 qa = *(const float4*)&qs[nn][tr * 4];
            float4 kb = *(const float4*)&ks[nn][tc * 4];
            float qv[4] = {qa.x, qa.y, qa.z, qa.w};
            float kv[4] = {kb.x, kb.y, kb.z, kb.w};
#pragma unroll
            for (int i = 0; i < 4; i++)
#pragma unroll
                for (int j = 0; j < 4; j++)
                    acc[i][j] = fmaf(qv[i], kv[j], acc[i][j]);
        }
        __syncthreads();
    }

    float* pp = g_partial + ((size_t)sp * NB * NHEADS + bh) * NCH * NCH;
#pragma unroll
    for (int i = 0; i < 4; i++)
#pragma unroll
        for (int j = 0; j < 4; j++)
            pp[(tr * 4 + i) * NCH + (tc * 4 + j)] = acc[i][j];
}

// ---------------- kernel 3: parallel reduce + softmax (256 thr / bh) ----------------
__global__ __launch_bounds__(256) void softmax_kernel(const float* __restrict__ temperature)
{
    __shared__ float sv[NCH * NCH];

    int bh = blockIdx.x;
    int h = bh & (NHEADS - 1);
    int tid = threadIdx.x;
    int lane = tid & 31;
    int warp = tid >> 5;

    float4 acc = make_float4(0.f, 0.f, 0.f, 0.f);
#pragma unroll 8
    for (int sp = 0; sp < NSPLIT; sp++) {
        const float* p = g_partial + ((size_t)sp * NB * NHEADS + bh) * (NCH * NCH) + tid * 4;
        float4 v = *(const float4*)p;
        acc.x += v.x; acc.y += v.y; acc.z += v.z; acc.w += v.w;
    }
    *(float4*)&sv[tid * 4] = acc;
    __syncthreads();

    float t = temperature[h];
#pragma unroll
    for (int r = 0; r < 4; r++) {
        int row = warp * 4 + r;
        float v = sv[row * NCH + lane] * t;
        float mx = v;
#pragma unroll
        for (int o = 16; o; o >>= 1) mx = fmaxf(mx, __shfl_xor_sync(0xffffffffu, mx, o));
        float e = __expf(v - mx);
        float s = e;
#pragma unroll
        for (int o = 16; o; o >>= 1) s += __shfl_xor_sync(0xffffffffu, s, o);
        g_attn[(size_t)bh * (NCH * NCH) + row * NCH + lane] = e / s;
    }
}

// ---------------- kernel P1: W_eff (32x32 tiles) + b_eff ----------------
__global__ __launch_bounds__(256) void weff_kernel(
    const float* __restrict__ fusion_w, const float* __restrict__ out_w,
    const float* __restrict__ out_b, const float* __restrict__ fusion_b,
    const float* __restrict__ gamma)
{
    __shared__ float Fs[32][33];
    __shared__ float Os[32][33];

    int f0 = (blockIdx.x >> 3) * 32;
    int c0 = (blockIdx.x & 7) * 32;
    int tid = threadIdx.x;
    int tx = tid & 15, ty = tid >> 4;

    if ((blockIdx.x & 7) == 0 && tid < 32) {
        int f = f0 + tid;
        float sb = 0.f;
        for (int o = 0; o < NC; o++)
            sb = fmaf(fusion_w[f * 2 * NC + o], out_b[o], sb);
        g_beff[f] = gamma[0] * sb + fusion_b[f];
    }

    float acc[2][2] = {};

    for (int ko = 0; ko < NC; ko += 32) {
#pragma unroll
        for (int r = 0; r < 4; r++) {
            int id = tid + r * 256;
            int ff = id >> 5, kk = id & 31;
            Fs[kk][ff] = fusion_w[(f0 + ff) * (2 * NC) + ko + kk];
            int kk2 = id >> 5, cc = id & 31;
            Os[kk2][cc] = out_w[(ko + kk2) * NC + c0 + cc];
        }
        __syncthreads();
#pragma unroll
        for (int k = 0; k < 32; k++) {
            float fv0 = Fs[k][ty * 2], fv1 = Fs[k][ty * 2 + 1];
            float ov0 = Os[k][tx * 2], ov1 = Os[k][tx * 2 + 1];
            acc[0][0] = fmaf(fv0, ov0, acc[0][0]);
            acc[0][1] = fmaf(fv0, ov1, acc[0][1]);
            acc[1][0] = fmaf(fv1, ov0, acc[1][0]);
            acc[1][1] = fmaf(fv1, ov1, acc[1][1]);
        }
        __syncthreads();
    }
    float g = gamma[0];
#pragma unroll
    for (int i = 0; i < 2; i++)
#pragma unroll
        for (int j = 0; j < 2; j++)
            g_weff[(f0 + ty * 2 + i) * NC + c0 + tx * 2 + j] = g * acc[i][j];
}

// ---------------- kernel P2: A_full -> single fp16 ----------------
__global__ __launch_bounds__(512) void afull_kernel(const float* __restrict__ fusion_w)
{
    int bf = blockIdx.x;
    int b = bf >> 8, f = bf & 255;
    int col = threadIdx.x;
    float v;
    if (col < NC) {
        int h = col >> 5, d = col & 31;
        const float* wrow = g_weff + f * NC + h * NCH;
        const float* arow = g_attn + ((size_t)(b * NHEADS + h) * NCH) * NCH + d;
        float s = 0.f;
#pragma unroll
        for (int cc = 0; cc < NCH; cc++)
            s = fmaf(wrow[cc], arow[cc * NCH], s);
        v = s;
    } else {
        v = fusion_w[f * 2 * NC + col];
    }
    g_af[(size_t)bf * 2 * NC + col] = __float2half_rn(v);
}

// ---------------- kernel 4: main GEMM — fp16 HMMA single product, cp.async 2-stage, BK=32 ----------------
// Y[b](256x16384) = A(256x512) @ B(512x16384) + b_eff
// BM=128, BN=128, BK=32, 256 threads = 8 warps (2m x 4n), warp tile 64x32.
#define AP 40     // A smem pitch: 80B rows -> conflict-free ldmatrix
#define BP 136    // B smem pitch: 272B rows -> conflict-free ldmatrix.trans
__global__ __launch_bounds__(256, 2) void main_gemm(float* __restrict__ y)
{
    __shared__ __align__(128) __half As[2][128][AP];   // [stage][m][k]
    __shared__ __align__(128) __half Bs[2][32][BP];    // [stage][k][n]

    int b  = blockIdx.z;
    int m0 = blockIdx.y * 128;
    int n0 = blockIdx.x * 128;
    int tid  = threadIdx.x;
    int lane = tid & 31;
    int warp = tid >> 5;
    int wm = (warp >> 2) * 64;
    int wn = (warp & 3) * 32;
    int g = lane >> 2;
    int t = lane & 3;

    int lr = lane & 15;
    int lc = (lane >> 4) * 8;

    const __half* gA = g_af + (size_t)(b * NC + m0) * (2 * NC);

    float acc[4][4][4];
#pragma unroll
    for (int i = 0; i < 4; i++)
#pragma unroll
        for (int j = 0; j < 4; j++)
#pragma unroll
            for (int r = 0; r < 4; r++) acc[i][j][r] = 0.f;

    auto load_stage = [&](int s, int it) {
        int k0 = it * 32;
        // A: 128 rows x 32 k = 512 chunks(16B), 2/thread
#pragma unroll
        for (int c = 0; c < 2; c++) {
            int id = tid + c * 256;
            int row = id >> 2;
            int kc = (id & 3) * 8;
            cpa16(&As[s][row][kc], gA + (size_t)row * (2 * NC) + k0 + kc);
        }
        // B: 32 k x 128 n = 512 chunks, 2/thread
#pragma unroll
        for (int c = 0; c < 2; c++) {
            int id = tid + c * 256;
            int krow = id >> 4;
            int nc = (id & 15) * 8;
            int grow = k0 + krow;
            const __half* src = (grow < NC)
                ? g_vf + (size_t)(b * NC + grow) * NPIX + n0 + nc
                : g_xf + (size_t)(b * NC + grow - NC) * NPIX + n0 + nc;
            cpa16(&Bs[s][krow][nc], src);
        }
        asm volatile("cp.async.commit_group;");
    };

    load_stage(0, 0);

    const int NIT = (2 * NC) / 32;   // 16
    for (int it = 0; it < NIT; it++) {
        int cur = it & 1;
        if (it + 1 < NIT) {
            load_stage(cur ^ 1, it + 1);
            asm volatile("cp.async.wait_group 1;");
        } else {
            asm volatile("cp.async.wait_group 0;");
        }
        __syncthreads();

#pragma unroll
        for (int ks = 0; ks < 2; ks++) {
            int kof = ks * 16;
            unsigned bh[4][2];
#pragma unroll
            for (int nb = 0; nb < 2; nb++) {
                unsigned d0, d1, d2, d3;
                ldsm4t(d0, d1, d2, d3, &Bs[cur][kof + lr][wn + nb * 16 + lc]);
                bh[nb * 2][0] = d0; bh[nb * 2][1] = d1;
                bh[nb * 2 + 1][0] = d2; bh[nb * 2 + 1][1] = d3;
            }
            unsigned af[4][4];
#pragma unroll
            for (int mf = 0; mf < 4; mf++)
                ldsm4(af[mf][0], af[mf][1], af[mf][2], af[mf][3],
                      &As[cur][wm + mf * 16 + lr][kof + lc]);
#pragma unroll
            for (int nf = 0; nf < 4; nf++)
#pragma unroll
                for (int mf = 0; mf < 4; mf++)
                    mma_f16(acc[mf][nf], af[mf], bh[nf]);
        }
        __syncthreads();
    }

    // epilogue
#pragma unroll
    for (int mf = 0; mf < 4; mf++) {
        int m = m0 + wm + mf * 16 + g;
        float be0 = g_beff[m];
        float be1 = g_beff[m + 8];
        float* yr0 = y + (size_t)(b * NC + m) * NPIX + n0 + wn;
        float* yr1 = yr0 + (size_t)8 * NPIX;
#pragma unroll
        for (int nf = 0; nf < 4; nf++) {
            *(float2*)(yr0 + nf * 8 + t * 2) =
                make_float2(acc[mf][nf][0] + be0, acc[mf][nf][1] + be0);
            *(float2*)(yr1 + nf * 8 + t * 2) =
                make_float2(acc[mf][nf][2] + be1, acc[mf][nf][3] + be1);
        }
    }
}

// ---------------- launch ----------------
extern "C" void kernel_launch(void* const* d_in, const int* in_sizes, int n_in,
                              void* d_out, int out_size)
{
    const float* x        = (const float*)d_in[0];
    const float* q_w      = (const float*)d_in[1];
    const float* q_b      = (const float*)d_in[2];
    const float* k_w      = (const float*)d_in[3];
    const float* k_b      = (const float*)d_in[4];
    const float* v_w      = (const float*)d_in[5];
    const float* v_b      = (const float*)d_in[6];
    const float* out_w    = (const float*)d_in[7];
    const float* out_b    = (const float*)d_in[8];
    const float* fusion_w = (const float*)d_in[9];
    const float* fusion_b = (const float*)d_in[10];
    const float* temperature = (const float*)d_in[11];
    const float* gamma    = (const float*)d_in[12];
    float* y = (float*)d_out;

    dwconv_qkv<<<NB * NC, 256>>>(x, q_w, q_b, k_w, k_b, v_w, v_b);

    dim3 ggrid(NB * NHEADS, NSPLIT);
    gram_kernel<<<ggrid, 64>>>();

    softmax_kernel<<<NB * NHEADS, 256>>>(temperature);

    weff_kernel<<<64, 256>>>(fusion_w, out_w, out_b, fusion_b, gamma);
    afull_kernel<<<NB * NC, 2 * NC>>>(fusion_w);

    dim3 mgrid(NPIX / 128, NC / 128, NB);
    main_gemm<<<mgrid, 256>>>(y);
}

// round 11
// speedup vs baseline: 3.9819x; 1.3862x over previous
#include <cuda_runtime.h>
#include <cuda_fp16.h>
#include <cstdint>

#define NB 4
#define NC 256
#define NH 128
#define NW 128
#define NPIX 16384
#define NHEADS 8
#define NCH 32
#define NSPLIT 32

// ---------------- scratch (static device memory; no allocations) ----------------
__device__ __half g_qf[NB * NC * NPIX];       // q fp16
__device__ __half g_kf[NB * NC * NPIX];       // k fp16
__device__ __half g_vf[NB * NC * NPIX];       // v fp16
__device__ __half g_xf[NB * NC * NPIX];       // x fp16
__device__ float g_partial[NSPLIT * NB * NHEADS * NCH * NCH];
__device__ float g_attn[NB * NHEADS * NCH * NCH];
__device__ float g_weff[NC * NC];
__device__ float g_beff[NC];
__device__ __half g_af[NB * NC * 2 * NC];     // A fp16

// ---------------- helpers ----------------
__device__ __forceinline__ unsigned pack_h2(__half a, __half b) {
    __half2 t; t.x = a; t.y = b;
    return *(unsigned*)&t;
}
__device__ __forceinline__ void mma_f16(float* d, const unsigned* a, const unsigned* b) {
    asm volatile(
        "mma.sync.aligned.m16n8k16.row.col.f32.f16.f16.f32 "
        "{%0,%1,%2,%3}, {%4,%5,%6,%7}, {%8,%9}, {%0,%1,%2,%3};"
        : "+f"(d[0]), "+f"(d[1]), "+f"(d[2]), "+f"(d[3])
        : "r"(a[0]), "r"(a[1]), "r"(a[2]), "r"(a[3]), "r"(b[0]), "r"(b[1]));
}
__device__ __forceinline__ void ldsm4(unsigned& d0, unsigned& d1, unsigned& d2, unsigned& d3,
                                      const void* p) {
    unsigned a = (unsigned)__cvta_generic_to_shared(p);
    asm volatile("ldmatrix.sync.aligned.m8n8.x4.shared.b16 {%0,%1,%2,%3},[%4];"
                 : "=r"(d0), "=r"(d1), "=r"(d2), "=r"(d3) : "r"(a));
}
__device__ __forceinline__ void ldsm4t(unsigned& d0, unsigned& d1, unsigned& d2, unsigned& d3,
                                       const void* p) {
    unsigned a = (unsigned)__cvta_generic_to_shared(p);
    asm volatile("ldmatrix.sync.aligned.m8n8.x4.trans.shared.b16 {%0,%1,%2,%3},[%4];"
                 : "=r"(d0), "=r"(d1), "=r"(d2), "=r"(d3) : "r"(a));
}
__device__ __forceinline__ void cpa16(void* s, const void* g) {
    unsigned sa = (unsigned)__cvta_generic_to_shared(s);
    asm volatile("cp.async.cg.shared.global [%0], [%1], 16;" :: "r"(sa), "l"(g));
}

// ---------------- kernel 1: dwconv 3x3 -> q,k,v,x all fp16 ----------------
__global__ __launch_bounds__(256) void dwconv_qkv(
    const float* __restrict__ x,
    const float* __restrict__ qw, const float* __restrict__ qb,
    const float* __restrict__ kw, const float* __restrict__ kb,
    const float* __restrict__ vw, const float* __restrict__ vb)
{
    int bc = blockIdx.x;
    int c  = bc & (NC - 1);
    const float* xp = x + (size_t)bc * NPIX;

    float wq[9], wk[9], wv[9];
#pragma unroll
    for (int t = 0; t < 9; t++) {
        wq[t] = qw[c * 9 + t];
        wk[t] = kw[c * 9 + t];
        wv[t] = vw[c * 9 + t];
    }
    float bq = qb[c], bk = kb[c], bv = vb[c];

    for (int p = threadIdx.x; p < NPIX / 4; p += 256) {
        int i  = p >> 5;
        int j0 = (p & 31) * 4;
        float l[3][6];
#pragma unroll
        for (int dy = 0; dy < 3; dy++) {
            int ii = i + dy - 1;
            if (ii < 0 || ii >= NH) {
#pragma unroll
                for (int t = 0; t < 6; t++) l[dy][t] = 0.f;
            } else {
                const float* rp = xp + ii * NW;
                l[dy][0] = (j0 > 0) ? __ldg(rp + j0 - 1) : 0.f;
                float4 m = *(const float4*)(rp + j0);
                l[dy][1] = m.x; l[dy][2] = m.y; l[dy][3] = m.z; l[dy][4] = m.w;
                l[dy][5] = (j0 + 4 < NW) ? __ldg(rp + j0 + 4) : 0.f;
            }
        }
        float oq[4], ok[4], ov[4];
#pragma unroll
        for (int e = 0; e < 4; e++) {
            float aq = bq, ak = bk, av = bv;
#pragma unroll
            for (int dy = 0; dy < 3; dy++)
#pragma unroll
                for (int dx = 0; dx < 3; dx++) {
                    float xv = l[dy][e + dx];
                    int t = dy * 3 + dx;
                    aq = fmaf(wq[t], xv, aq);
                    ak = fmaf(wk[t], xv, ak);
                    av = fmaf(wv[t], xv, av);
                }
            oq[e] = aq; ok[e] = ak; ov[e] = av;
        }
        size_t o = (size_t)bc * NPIX + (size_t)p * 4;
        *(uint2*)(g_qf + o) = make_uint2(
            pack_h2(__float2half_rn(oq[0]), __float2half_rn(oq[1])),
            pack_h2(__float2half_rn(oq[2]), __float2half_rn(oq[3])));
        *(uint2*)(g_kf + o) = make_uint2(
            pack_h2(__float2half_rn(ok[0]), __float2half_rn(ok[1])),
            pack_h2(__float2half_rn(ok[2]), __float2half_rn(ok[3])));
        *(uint2*)(g_vf + o) = make_uint2(
            pack_h2(__float2half_rn(ov[0]), __float2half_rn(ov[1])),
            pack_h2(__float2half_rn(ov[2]), __float2half_rn(ov[3])));
        *(uint2*)(g_xf + o) = make_uint2(
            pack_h2(__float2half_rn(l[1][1]), __float2half_rn(l[1][2])),
            pack_h2(__float2half_rn(l[1][3]), __float2half_rn(l[1][4])));
    }
}

// ---------------- kernel 2: tensor-core gram S = Q K^T (fp16 in, fp32 acc) ----------------
// grid (bh=32, sp=32 x 512px), 128 threads = 4 warps; warp w owns n-cols 8w..8w+7, full m=32.
#define QP 72   // smem pitch (halves): 144B rows -> conflict-free ldmatrix
__global__ __launch_bounds__(128) void gram_tc()
{
    __shared__ __align__(128) __half qs[2][NCH][QP];
    __shared__ __align__(128) __half ks[2][NCH][QP];

    int bh = blockIdx.x;
    int sp = blockIdx.y;
    int p0 = sp * (NPIX / NSPLIT);    // 512 px per split
    int tid = threadIdx.x;
    int lane = tid & 31;
    int warp = tid >> 5;

    const __half* qp = g_qf + (size_t)bh * NCH * NPIX;
    const __half* kp = g_kf + (size_t)bh * NCH * NPIX;

    float acc[2][4] = {};   // [m-tile][c0..c3]

    auto load_tile = [&](int s, int t0) {
        // q,k tiles: 32 rows x 64 px = 256 16B-chunks each; 2+2 per thread
#pragma unroll
        for (int r = 0; r < 2; r++) {
            int id = tid + r * 128;
            int ch = id >> 3;
            int pc = id & 7;
            cpa16(&qs[s][ch][pc * 8], qp + (size_t)ch * NPIX + t0 + pc * 8);
            cpa16(&ks[s][ch][pc * 8], kp + (size_t)ch * NPIX + t0 + pc * 8);
        }
        asm volatile("cp.async.commit_group;");
    };

    load_tile(0, p0);

    int lr = lane & 15;            // A ldmatrix row
    int lc = (lane >> 4) * 8;      // A ldmatrix k-offset (halves)
    int brow = warp * 8 + (lane & 7);      // B ldmatrix row (n)
    int bcol = (lane >> 3) * 8;            // B ldmatrix k-offset (halves), covers k32

    for (int t = 0; t < 8; t++) {
        int cur = t & 1;
        if (t + 1 < 8) {
            load_tile(cur ^ 1, p0 + (t + 1) * 64);
            asm volatile("cp.async.wait_group 1;");
        } else {
            asm volatile("cp.async.wait_group 0;");
        }
        __syncthreads();

#pragma unroll
        for (int s2 = 0; s2 < 2; s2++) {       // two k32 steps per 64-px tile
            int px = s2 * 32;
            unsigned b4[4];
            ldsm4(b4[0], b4[1], b4[2], b4[3], &ks[cur][brow][px + bcol]);
#pragma unroll
            for (int ks16 = 0; ks16 < 2; ks16++) {   // two k16 sub-steps
                unsigned a0[4], a1[4];
                ldsm4(a0[0], a0[1], a0[2], a0[3], &qs[cur][lr][px + ks16 * 16 + lc]);
                ldsm4(a1[0], a1[1], a1[2], a1[3], &qs[cur][16 + lr][px + ks16 * 16 + lc]);
                mma_f16(acc[0], a0, b4 + ks16 * 2);
                mma_f16(acc[1], a1, b4 + ks16 * 2);
            }
        }
        __syncthreads();
    }

    // write partials: fragment layout c0:(g,2t) c1:(g,2t+1) c2:(g+8,2t) c3:(g+8,2t+1)
    float* pp = g_partial + ((size_t)sp * NB * NHEADS + bh) * (NCH * NCH);
    int g = lane >> 2, tt = lane & 3;
#pragma unroll
    for (int mt = 0; mt < 2; mt++) {
        int m = mt * 16 + g;
        int n = warp * 8 + tt * 2;
        pp[m * NCH + n]           = acc[mt][0];
        pp[m * NCH + n + 1]       = acc[mt][1];
        pp[(m + 8) * NCH + n]     = acc[mt][2];
        pp[(m + 8) * NCH + n + 1] = acc[mt][3];
    }
}

// ---------------- kernel 3: parallel reduce + softmax (256 thr / bh) ----------------
__global__ __launch_bounds__(256) void softmax_kernel(const float* __restrict__ temperature)
{
    __shared__ float sv[NCH * NCH];

    int bh = blockIdx.x;
    int h = bh & (NHEADS - 1);
    int tid = threadIdx.x;
    int lane = tid & 31;
    int warp = tid >> 5;

    float4 acc = make_float4(0.f, 0.f, 0.f, 0.f);
#pragma unroll 8
    for (int sp = 0; sp < NSPLIT; sp++) {
        const float* p = g_partial + ((size_t)sp * NB * NHEADS + bh) * (NCH * NCH) + tid * 4;
        float4 v = *(const float4*)p;
        acc.x += v.x; acc.y += v.y; acc.z += v.z; acc.w += v.w;
    }
    *(float4*)&sv[tid * 4] = acc;
    __syncthreads();

    float t = temperature[h];
#pragma unroll
    for (int r = 0; r < 4; r++) {
        int row = warp * 4 + r;
        float v = sv[row * NCH + lane] * t;
        float mx = v;
#pragma unroll
        for (int o = 16; o; o >>= 1) mx = fmaxf(mx, __shfl_xor_sync(0xffffffffu, mx, o));
        float e = __expf(v - mx);
        float s = e;
#pragma unroll
        for (int o = 16; o; o >>= 1) s += __shfl_xor_sync(0xffffffffu, s, o);
        g_attn[(size_t)bh * (NCH * NCH) + row * NCH + lane] = e / s;
    }
}

// ---------------- kernel P1: W_eff (32x32 tiles) + b_eff ----------------
__global__ __launch_bounds__(256) void weff_kernel(
    const float* __restrict__ fusion_w, const float* __restrict__ out_w,
    const float* __restrict__ out_b, const float* __restrict__ fusion_b,
    const float* __restrict__ gamma)
{
    __shared__ float Fs[32][33];
    __shared__ float Os[32][33];

    int f0 = (blockIdx.x >> 3) * 32;
    int c0 = (blockIdx.x & 7) * 32;
    int tid = threadIdx.x;
    int tx = tid & 15, ty = tid >> 4;

    if ((blockIdx.x & 7) == 0 && tid < 32) {
        int f = f0 + tid;
        float sb = 0.f;
        for (int o = 0; o < NC; o++)
            sb = fmaf(fusion_w[f * 2 * NC + o], out_b[o], sb);
        g_beff[f] = gamma[0] * sb + fusion_b[f];
    }

    float acc[2][2] = {};

    for (int ko = 0; ko < NC; ko += 32) {
#pragma unroll
        for (int r = 0; r < 4; r++) {
            int id = tid + r * 256;
            int ff = id >> 5, kk = id & 31;
            Fs[kk][ff] = fusion_w[(f0 + ff) * (2 * NC) + ko + kk];
            int kk2 = id >> 5, cc = id & 31;
            Os[kk2][cc] = out_w[(ko + kk2) * NC + c0 + cc];
        }
        __syncthreads();
#pragma unroll
        for (int k = 0; k < 32; k++) {
            float fv0 = Fs[k][ty * 2], fv1 = Fs[k][ty * 2 + 1];
            float ov0 = Os[k][tx * 2], ov1 = Os[k][tx * 2 + 1];
            acc[0][0] = fmaf(fv0, ov0, acc[0][0]);
            acc[0][1] = fmaf(fv0, ov1, acc[0][1]);
            acc[1][0] = fmaf(fv1, ov0, acc[1][0]);
            acc[1][1] = fmaf(fv1, ov1, acc[1][1]);
        }
        __syncthreads();
    }
    float g = gamma[0];
#pragma unroll
    for (int i = 0; i < 2; i++)
#pragma unroll
        for (int j = 0; j < 2; j++)
            g_weff[(f0 + ty * 2 + i) * NC + c0 + tx * 2 + j] = g * acc[i][j];
}

// ---------------- kernel P2: A_full -> fp16 ----------------
__global__ __launch_bounds__(512) void afull_kernel(const float* __restrict__ fusion_w)
{
    int bf = blockIdx.x;
    int b = bf >> 8, f = bf & 255;
    int col = threadIdx.x;
    float v;
    if (col < NC) {
        int h = col >> 5, d = col & 31;
        const float* wrow = g_weff + f * NC + h * NCH;
        const float* arow = g_attn + ((size_t)(b * NHEADS + h) * NCH) * NCH + d;
        float s = 0.f;
#pragma unroll
        for (int cc = 0; cc < NCH; cc++)
            s = fmaf(wrow[cc], arow[cc * NCH], s);
        v = s;
    } else {
        v = fusion_w[f * 2 * NC + col];
    }
    g_af[(size_t)bf * 2 * NC + col] = __float2half_rn(v);
}

// ---------------- kernel 4: main GEMM — fp16 HMMA, cp.async 2-stage, BK=32 ----------------
#define AP 40     // A smem pitch: 80B rows -> conflict-free ldmatrix
#define BP 136    // B smem pitch: 272B rows -> conflict-free ldmatrix.trans
__global__ __launch_bounds__(256, 2) void main_gemm(float* __restrict__ y)
{
    __shared__ __align__(128) __half As[2][128][AP];
    __shared__ __align__(128) __half Bs[2][32][BP];

    int b  = blockIdx.z;
    int m0 = blockIdx.y * 128;
    int n0 = blockIdx.x * 128;
    int tid  = threadIdx.x;
    int lane = tid & 31;
    int warp = tid >> 5;
    int wm = (warp >> 2) * 64;
    int wn = (warp & 3) * 32;
    int g = lane >> 2;
    int t = lane & 3;

    int lr = lane & 15;
    int lc = (lane >> 4) * 8;

    const __half* gA = g_af + (size_t)(b * NC + m0) * (2 * NC);

    float acc[4][4][4];
#pragma unroll
    for (int i = 0; i < 4; i++)
#pragma unroll
        for (int j = 0; j < 4; j++)
#pragma unroll
            for (int r = 0; r < 4; r++) acc[i][j][r] = 0.f;

    auto load_stage = [&](int s, int it) {
        int k0 = it * 32;
#pragma unroll
        for (int c = 0; c < 2; c++) {
            int id = tid + c * 256;
            int row = id >> 2;
            int kc = (id & 3) * 8;
            cpa16(&As[s][row][kc], gA + (size_t)row * (2 * NC) + k0 + kc);
        }
#pragma unroll
        for (int c = 0; c < 2; c++) {
            int id = tid + c * 256;
            int krow = id >> 4;
            int nc = (id & 15) * 8;
            int grow = k0 + krow;
            const __half* src = (grow < NC)
                ? g_vf + (size_t)(b * NC + grow) * NPIX + n0 + nc
                : g_xf + (size_t)(b * NC + grow - NC) * NPIX + n0 + nc;
            cpa16(&Bs[s][krow][nc], src);
        }
        asm volatile("cp.async.commit_group;");
    };

    load_stage(0, 0);

    const int NIT = (2 * NC) / 32;
    for (int it = 0; it < NIT; it++) {
        int cur = it & 1;
        if (it + 1 < NIT) {
            load_stage(cur ^ 1, it + 1);
            asm volatile("cp.async.wait_group 1;");
        } else {
            asm volatile("cp.async.wait_group 0;");
        }
        __syncthreads();

#pragma unroll
        for (int ks = 0; ks < 2; ks++) {
            int kof = ks * 16;
            unsigned bh[4][2];
#pragma unroll
            for (int nb = 0; nb < 2; nb++) {
                unsigned d0, d1, d2, d3;
                ldsm4t(d0, d1, d2, d3, &Bs[cur][kof + lr][wn + nb * 16 + lc]);
                bh[nb * 2][0] = d0; bh[nb * 2][1] = d1;
                bh[nb * 2 + 1][0] = d2; bh[nb * 2 + 1][1] = d3;
            }
            unsigned af[4][4];
#pragma unroll
            for (int mf = 0; mf < 4; mf++)
                ldsm4(af[mf][0], af[mf][1], af[mf][2], af[mf][3],
                      &As[cur][wm + mf * 16 + lr][kof + lc]);
#pragma unroll
            for (int nf = 0; nf < 4; nf++)
#pragma unroll
                for (int mf = 0; mf < 4; mf++)
                    mma_f16(acc[mf][nf], af[mf], bh[nf]);
        }
        __syncthreads();
    }

#pragma unroll
    for (int mf = 0; mf < 4; mf++) {
        int m = m0 + wm + mf * 16 + g;
        float be0 = g_beff[m];
        float be1 = g_beff[m + 8];
        float* yr0 = y + (size_t)(b * NC + m) * NPIX + n0 + wn;
        float* yr1 = yr0 + (size_t)8 * NPIX;
#pragma unroll
        for (int nf = 0; nf < 4; nf++) {
            *(float2*)(yr0 + nf * 8 + t * 2) =
                make_float2(acc[mf][nf][0] + be0, acc[mf][nf][1] + be0);
            *(float2*)(yr1 + nf * 8 + t * 2) =
                make_float2(acc[mf][nf][2] + be1, acc[mf][nf][3] + be1);
        }
    }
}

// ---------------- launch ----------------
extern "C" void kernel_launch(void* const* d_in, const int* in_sizes, int n_in,
                              void* d_out, int out_size)
{
    const float* x        = (const float*)d_in[0];
    const float* q_w      = (const float*)d_in[1];
    const float* q_b      = (const float*)d_in[2];
    const float* k_w      = (const float*)d_in[3];
    const float* k_b      = (const float*)d_in[4];
    const float* v_w      = (const float*)d_in[5];
    const float* v_b      = (const float*)d_in[6];
    const float* out_w    = (const float*)d_in[7];
    const float* out_b    = (const float*)d_in[8];
    const float* fusion_w = (const float*)d_in[9];
    const float* fusion_b = (const float*)d_in[10];
    const float* temperature = (const float*)d_in[11];
    const float* gamma    = (const float*)d_in[12];
    float* y = (float*)d_out;

    dwconv_qkv<<<NB * NC, 256>>>(x, q_w, q_b, k_w, k_b, v_w, v_b);

    dim3 ggrid(NB * NHEADS, NSPLIT);
    gram_tc<<<ggrid, 128>>>();

    softmax_kernel<<<NB * NHEADS, 256>>>(temperature);

    weff_kernel<<<64, 256>>>(fusion_w, out_w, out_b, fusion_b, gamma);
    afull_kernel<<<NB * NC, 2 * NC>>>(fusion_w);

    dim3 mgrid(NPIX / 128, NC / 128, NB);
    main_gemm<<<mgrid, 256>>>(y);
}

// round 12
// speedup vs baseline: 4.1331x; 1.0380x over previous
#include <cuda_runtime.h>
#include <cuda_fp16.h>
#include <cstdint>

#define NB 4
#define NC 256
#define NH 128
#define NW 128
#define NPIX 16384
#define NHEADS 8
#define NCH 32
#define NSPLIT 32

// ---------------- scratch (static device memory; no allocations) ----------------
__device__ __half g_qf[NB * NC * NPIX];       // q fp16
__device__ __half g_kf[NB * NC * NPIX];       // k fp16
__device__ __half g_vf[NB * NC * NPIX];       // v fp16
__device__ __half g_xf[NB * NC * NPIX];       // x fp16
__device__ float g_partial[NSPLIT * NB * NHEADS * NCH * NCH];
__device__ float g_attn[NB * NHEADS * NCH * NCH];
__device__ float g_weff[NC * NC];
__device__ float g_beff[NC];
__device__ __half g_af[NB * NC * 2 * NC];     // A fp16

// ---------------- helpers ----------------
__device__ __forceinline__ unsigned pack_h2(__half a, __half b) {
    __half2 t; t.x = a; t.y = b;
    return *(unsigned*)&t;
}
__device__ __forceinline__ void mma_f16(float* d, const unsigned* a, const unsigned* b) {
    asm volatile(
        "mma.sync.aligned.m16n8k16.row.col.f32.f16.f16.f32 "
        "{%0,%1,%2,%3}, {%4,%5,%6,%7}, {%8,%9}, {%0,%1,%2,%3};"
        : "+f"(d[0]), "+f"(d[1]), "+f"(d[2]), "+f"(d[3])
        : "r"(a[0]), "r"(a[1]), "r"(a[2]), "r"(a[3]), "r"(b[0]), "r"(b[1]));
}
__device__ __forceinline__ void ldsm4(unsigned& d0, unsigned& d1, unsigned& d2, unsigned& d3,
                                      const void* p) {
    unsigned a = (unsigned)__cvta_generic_to_shared(p);
    asm volatile("ldmatrix.sync.aligned.m8n8.x4.shared.b16 {%0,%1,%2,%3},[%4];"
                 : "=r"(d0), "=r"(d1), "=r"(d2), "=r"(d3) : "r"(a));
}
__device__ __forceinline__ void ldsm4t(unsigned& d0, unsigned& d1, unsigned& d2, unsigned& d3,
                                       const void* p) {
    unsigned a = (unsigned)__cvta_generic_to_shared(p);
    asm volatile("ldmatrix.sync.aligned.m8n8.x4.trans.shared.b16 {%0,%1,%2,%3},[%4];"
                 : "=r"(d0), "=r"(d1), "=r"(d2), "=r"(d3) : "r"(a));
}
__device__ __forceinline__ void cpa16(void* s, const void* g) {
    unsigned sa = (unsigned)__cvta_generic_to_shared(s);
    asm volatile("cp.async.cg.shared.global [%0], [%1], 16;" :: "r"(sa), "l"(g));
}

// ---------------- kernel 1: dwconv 3x3 -> q,k,v,x all fp16 ----------------
__global__ __launch_bounds__(256) void dwconv_qkv(
    const float* __restrict__ x,
    const float* __restrict__ qw, const float* __restrict__ qb,
    const float* __restrict__ kw, const float* __restrict__ kb,
    const float* __restrict__ vw, const float* __restrict__ vb)
{
    int bc = blockIdx.x;
    int c  = bc & (NC - 1);
    const float* xp = x + (size_t)bc * NPIX;

    float wq[9], wk[9], wv[9];
#pragma unroll
    for (int t = 0; t < 9; t++) {
        wq[t] = qw[c * 9 + t];
        wk[t] = kw[c * 9 + t];
        wv[t] = vw[c * 9 + t];
    }
    float bq = qb[c], bk = kb[c], bv = vb[c];

    for (int p = threadIdx.x; p < NPIX / 4; p += 256) {
        int i  = p >> 5;
        int j0 = (p & 31) * 4;
        float l[3][6];
#pragma unroll
        for (int dy = 0; dy < 3; dy++) {
            int ii = i + dy - 1;
            if (ii < 0 || ii >= NH) {
#pragma unroll
                for (int t = 0; t < 6; t++) l[dy][t] = 0.f;
            } else {
                const float* rp = xp + ii * NW;
                l[dy][0] = (j0 > 0) ? __ldg(rp + j0 - 1) : 0.f;
                float4 m = *(const float4*)(rp + j0);
                l[dy][1] = m.x; l[dy][2] = m.y; l[dy][3] = m.z; l[dy][4] = m.w;
                l[dy][5] = (j0 + 4 < NW) ? __ldg(rp + j0 + 4) : 0.f;
            }
        }
        float oq[4], ok[4], ov[4];
#pragma unroll
        for (int e = 0; e < 4; e++) {
            float aq = bq, ak = bk, av = bv;
#pragma unroll
            for (int dy = 0; dy < 3; dy++)
#pragma unroll
                for (int dx = 0; dx < 3; dx++) {
                    float xv = l[dy][e + dx];
                    int t = dy * 3 + dx;
                    aq = fmaf(wq[t], xv, aq);
                    ak = fmaf(wk[t], xv, ak);
                    av = fmaf(wv[t], xv, av);
                }
            oq[e] = aq; ok[e] = ak; ov[e] = av;
        }
        size_t o = (size_t)bc * NPIX + (size_t)p * 4;
        *(uint2*)(g_qf + o) = make_uint2(
            pack_h2(__float2half_rn(oq[0]), __float2half_rn(oq[1])),
            pack_h2(__float2half_rn(oq[2]), __float2half_rn(oq[3])));
        *(uint2*)(g_kf + o) = make_uint2(
            pack_h2(__float2half_rn(ok[0]), __float2half_rn(ok[1])),
            pack_h2(__float2half_rn(ok[2]), __float2half_rn(ok[3])));
        *(uint2*)(g_vf + o) = make_uint2(
            pack_h2(__float2half_rn(ov[0]), __float2half_rn(ov[1])),
            pack_h2(__float2half_rn(ov[2]), __float2half_rn(ov[3])));
        *(uint2*)(g_xf + o) = make_uint2(
            pack_h2(__float2half_rn(l[1][1]), __float2half_rn(l[1][2])),
            pack_h2(__float2half_rn(l[1][3]), __float2half_rn(l[1][4])));
    }
}

// ---------------- kernel 2: tensor-core gram S = Q K^T (fp16 in, fp32 acc) ----------------
#define QP 72   // smem pitch (halves): 144B rows -> conflict-free ldmatrix
__global__ __launch_bounds__(128) void gram_tc()
{
    __shared__ __align__(128) __half qs[2][NCH][QP];
    __shared__ __align__(128) __half ks[2][NCH][QP];

    int bh = blockIdx.x;
    int sp = blockIdx.y;
    int p0 = sp * (NPIX / NSPLIT);
    int tid = threadIdx.x;
    int lane = tid & 31;
    int warp = tid >> 5;

    const __half* qp = g_qf + (size_t)bh * NCH * NPIX;
    const __half* kp = g_kf + (size_t)bh * NCH * NPIX;

    float acc[2][4] = {};

    auto load_tile = [&](int s, int t0) {
#pragma unroll
        for (int r = 0; r < 2; r++) {
            int id = tid + r * 128;
            int ch = id >> 3;
            int pc = id & 7;
            cpa16(&qs[s][ch][pc * 8], qp + (size_t)ch * NPIX + t0 + pc * 8);
            cpa16(&ks[s][ch][pc * 8], kp + (size_t)ch * NPIX + t0 + pc * 8);
        }
        asm volatile("cp.async.commit_group;");
    };

    load_tile(0, p0);

    int lr = lane & 15;
    int lc = (lane >> 4) * 8;
    int brow = warp * 8 + (lane & 7);
    int bcol = (lane >> 3) * 8;

    for (int t = 0; t < 8; t++) {
        int cur = t & 1;
        if (t + 1 < 8) {
            load_tile(cur ^ 1, p0 + (t + 1) * 64);
            asm volatile("cp.async.wait_group 1;");
        } else {
            asm volatile("cp.async.wait_group 0;");
        }
        __syncthreads();

#pragma unroll
        for (int s2 = 0; s2 < 2; s2++) {
            int px = s2 * 32;
            unsigned b4[4];
            ldsm4(b4[0], b4[1], b4[2], b4[3], &ks[cur][brow][px + bcol]);
#pragma unroll
            for (int ks16 = 0; ks16 < 2; ks16++) {
                unsigned a0[4], a1[4];
                ldsm4(a0[0], a0[1], a0[2], a0[3], &qs[cur][lr][px + ks16 * 16 + lc]);
                ldsm4(a1[0], a1[1], a1[2], a1[3], &qs[cur][16 + lr][px + ks16 * 16 + lc]);
                mma_f16(acc[0], a0, b4 + ks16 * 2);
                mma_f16(acc[1], a1, b4 + ks16 * 2);
            }
        }
        __syncthreads();
    }

    float* pp = g_partial + ((size_t)sp * NB * NHEADS + bh) * (NCH * NCH);
    int g = lane >> 2, tt = lane & 3;
#pragma unroll
    for (int mt = 0; mt < 2; mt++) {
        int m = mt * 16 + g;
        int n = warp * 8 + tt * 2;
        pp[m * NCH + n]           = acc[mt][0];
        pp[m * NCH + n + 1]       = acc[mt][1];
        pp[(m + 8) * NCH + n]     = acc[mt][2];
        pp[(m + 8) * NCH + n + 1] = acc[mt][3];
    }
}

// ---------------- kernel 3: parallel reduce + softmax (256 thr / bh) ----------------
__global__ __launch_bounds__(256) void softmax_kernel(const float* __restrict__ temperature)
{
    __shared__ float sv[NCH * NCH];

    int bh = blockIdx.x;
    int h = bh & (NHEADS - 1);
    int tid = threadIdx.x;
    int lane = tid & 31;
    int warp = tid >> 5;

    float4 acc = make_float4(0.f, 0.f, 0.f, 0.f);
#pragma unroll 8
    for (int sp = 0; sp < NSPLIT; sp++) {
        const float* p = g_partial + ((size_t)sp * NB * NHEADS + bh) * (NCH * NCH) + tid * 4;
        float4 v = *(const float4*)p;
        acc.x += v.x; acc.y += v.y; acc.z += v.z; acc.w += v.w;
    }
    *(float4*)&sv[tid * 4] = acc;
    __syncthreads();

    float t = temperature[h];
#pragma unroll
    for (int r = 0; r < 4; r++) {
        int row = warp * 4 + r;
        float v = sv[row * NCH + lane] * t;
        float mx = v;
#pragma unroll
        for (int o = 16; o; o >>= 1) mx = fmaxf(mx, __shfl_xor_sync(0xffffffffu, mx, o));
        float e = __expf(v - mx);
        float s = e;
#pragma unroll
        for (int o = 16; o; o >>= 1) s += __shfl_xor_sync(0xffffffffu, s, o);
        g_attn[(size_t)bh * (NCH * NCH) + row * NCH + lane] = e / s;
    }
}

// ---------------- kernel P1: W_eff (32x32 tiles) + b_eff ----------------
__global__ __launch_bounds__(256) void weff_kernel(
    const float* __restrict__ fusion_w, const float* __restrict__ out_w,
    const float* __restrict__ out_b, const float* __restrict__ fusion_b,
    const float* __restrict__ gamma)
{
    __shared__ float Fs[32][33];
    __shared__ float Os[32][33];

    int f0 = (blockIdx.x >> 3) * 32;
    int c0 = (blockIdx.x & 7) * 32;
    int tid = threadIdx.x;
    int tx = tid & 15, ty = tid >> 4;

    if ((blockIdx.x & 7) == 0 && tid < 32) {
        int f = f0 + tid;
        float sb = 0.f;
        for (int o = 0; o < NC; o++)
            sb = fmaf(fusion_w[f * 2 * NC + o], out_b[o], sb);
        g_beff[f] = gamma[0] * sb + fusion_b[f];
    }

    float acc[2][2] = {};

    for (int ko = 0; ko < NC; ko += 32) {
#pragma unroll
        for (int r = 0; r < 4; r++) {
            int id = tid + r * 256;
            int ff = id >> 5, kk = id & 31;
            Fs[kk][ff] = fusion_w[(f0 + ff) * (2 * NC) + ko + kk];
            int kk2 = id >> 5, cc = id & 31;
            Os[kk2][cc] = out_w[(ko + kk2) * NC + c0 + cc];
        }
        __syncthreads();
#pragma unroll
        for (int k = 0; k < 32; k++) {
            float fv0 = Fs[k][ty * 2], fv1 = Fs[k][ty * 2 + 1];
            float ov0 = Os[k][tx * 2], ov1 = Os[k][tx * 2 + 1];
            acc[0][0] = fmaf(fv0, ov0, acc[0][0]);
            acc[0][1] = fmaf(fv0, ov1, acc[0][1]);
            acc[1][0] = fmaf(fv1, ov0, acc[1][0]);
            acc[1][1] = fmaf(fv1, ov1, acc[1][1]);
        }
        __syncthreads();
    }
    float g = gamma[0];
#pragma unroll
    for (int i = 0; i < 2; i++)
#pragma unroll
        for (int j = 0; j < 2; j++)
            g_weff[(f0 + ty * 2 + i) * NC + c0 + tx * 2 + j] = g * acc[i][j];
}

// ---------------- kernel P2: A_full -> fp16 ----------------
__global__ __launch_bounds__(512) void afull_kernel(const float* __restrict__ fusion_w)
{
    int bf = blockIdx.x;
    int b = bf >> 8, f = bf & 255;
    int col = threadIdx.x;
    float v;
    if (col < NC) {
        int h = col >> 5, d = col & 31;
        const float* wrow = g_weff + f * NC + h * NCH;
        const float* arow = g_attn + ((size_t)(b * NHEADS + h) * NCH) * NCH + d;
        float s = 0.f;
#pragma unroll
        for (int cc = 0; cc < NCH; cc++)
            s = fmaf(wrow[cc], arow[cc * NCH], s);
        v = s;
    } else {
        v = fusion_w[f * 2 * NC + col];
    }
    g_af[(size_t)bf * 2 * NC + col] = __float2half_rn(v);
}

// ---------------- kernel 4: main GEMM — fp16 HMMA, cp.async 2-stage, BK=64 ----------------
// BM=128, BN=128, BK=64, 256 threads = 8 warps (2m x 4n), warp tile 64x32. 8 iterations.
#define AP 72     // A smem pitch (halves): 144B rows -> conflict-free ldmatrix
#define BP 136    // B smem pitch (halves): 272B rows -> conflict-free ldmatrix.trans
__global__ __launch_bounds__(256, 2) void main_gemm(float* __restrict__ y)
{
    __shared__ __align__(128) __half As[2][128][AP];
    __shared__ __align__(128) __half Bs[2][64][BP];

    int b  = blockIdx.z;
    int m0 = blockIdx.y * 128;
    int n0 = blockIdx.x * 128;
    int tid  = threadIdx.x;
    int lane = tid & 31;
    int warp = tid >> 5;
    int wm = (warp >> 2) * 64;
    int wn = (warp & 3) * 32;
    int g = lane >> 2;
    int t = lane & 3;

    int lr = lane & 15;
    int lc = (lane >> 4) * 8;

    const __half* gA = g_af + (size_t)(b * NC + m0) * (2 * NC);

    float acc[4][4][4];
#pragma unroll
    for (int i = 0; i < 4; i++)
#pragma unroll
        for (int j = 0; j < 4; j++)
#pragma unroll
            for (int r = 0; r < 4; r++) acc[i][j][r] = 0.f;

    auto load_stage = [&](int s, int it) {
        int k0 = it * 64;
        // A: 128 rows x 64 halves = 1024 16B-chunks, 4/thread
#pragma unroll
        for (int c = 0; c < 4; c++) {
            int id = tid + c * 256;
            int row = id >> 3;
            int kc = (id & 7) * 8;
            cpa16(&As[s][row][kc], gA + (size_t)row * (2 * NC) + k0 + kc);
        }
        // B: 64 k-rows x 128 halves = 1024 chunks, 4/thread
#pragma unroll
        for (int c = 0; c < 4; c++) {
            int id = tid + c * 256;
            int krow = id >> 4;
            int nc = (id & 15) * 8;
            int grow = k0 + krow;
            const __half* src = (grow < NC)
                ? g_vf + (size_t)(b * NC + grow) * NPIX + n0 + nc
                : g_xf + (size_t)(b * NC + grow - NC) * NPIX + n0 + nc;
            cpa16(&Bs[s][krow][nc], src);
        }
        asm volatile("cp.async.commit_group;");
    };

    load_stage(0, 0);

    const int NIT = (2 * NC) / 64;   // 8
    for (int it = 0; it < NIT; it++) {
        int cur = it & 1;
        if (it + 1 < NIT) {
            load_stage(cur ^ 1, it + 1);
            asm volatile("cp.async.wait_group 1;");
        } else {
            asm volatile("cp.async.wait_group 0;");
        }
        __syncthreads();

#pragma unroll
        for (int ks = 0; ks < 4; ks++) {
            int kof = ks * 16;
            unsigned bh[4][2];
#pragma unroll
            for (int nb = 0; nb < 2; nb++) {
                unsigned d0, d1, d2, d3;
                ldsm4t(d0, d1, d2, d3, &Bs[cur][kof + lr][wn + nb * 16 + lc]);
                bh[nb * 2][0] = d0; bh[nb * 2][1] = d1;
                bh[nb * 2 + 1][0] = d2; bh[nb * 2 + 1][1] = d3;
            }
            unsigned af[4][4];
#pragma unroll
            for (int mf = 0; mf < 4; mf++)
                ldsm4(af[mf][0], af[mf][1], af[mf][2], af[mf][3],
                      &As[cur][wm + mf * 16 + lr][kof + lc]);
#pragma unroll
            for (int nf = 0; nf < 4; nf++)
#pragma unroll
                for (int mf = 0; mf < 4; mf++)
                    mma_f16(acc[mf][nf], af[mf], bh[nf]);
        }
        __syncthreads();
    }

#pragma unroll
    for (int mf = 0; mf < 4; mf++) {
        int m = m0 + wm + mf * 16 + g;
        float be0 = g_beff[m];
        float be1 = g_beff[m + 8];
        float* yr0 = y + (size_t)(b * NC + m) * NPIX + n0 + wn;
        float* yr1 = yr0 + (size_t)8 * NPIX;
#pragma unroll
        for (int nf = 0; nf < 4; nf++) {
            *(float2*)(yr0 + nf * 8 + t * 2) =
                make_float2(acc[mf][nf][0] + be0, acc[mf][nf][1] + be0);
            *(float2*)(yr1 + nf * 8 + t * 2) =
                make_float2(acc[mf][nf][2] + be1, acc[mf][nf][3] + be1);
        }
    }
}

// ---------------- launch ----------------
extern "C" void kernel_launch(void* const* d_in, const int* in_sizes, int n_in,
                              void* d_out, int out_size)
{
    const float* x        = (const float*)d_in[0];
    const float* q_w      = (const float*)d_in[1];
    const float* q_b      = (const float*)d_in[2];
    const float* k_w      = (const float*)d_in[3];
    const float* k_b      = (const float*)d_in[4];
    const float* v_w      = (const float*)d_in[5];
    const float* v_b      = (const float*)d_in[6];
    const float* out_w    = (const float*)d_in[7];
    const float* out_b    = (const float*)d_in[8];
    const float* fusion_w = (const float*)d_in[9];
    const float* fusion_b = (const float*)d_in[10];
    const float* temperature = (const float*)d_in[11];
    const float* gamma    = (const float*)d_in[12];
    float* y = (float*)d_out;

    dwconv_qkv<<<NB * NC, 256>>>(x, q_w, q_b, k_w, k_b, v_w, v_b);

    dim3 ggrid(NB * NHEADS, NSPLIT);
    gram_tc<<<ggrid, 128>>>();

    softmax_kernel<<<NB * NHEADS, 256>>>(temperature);

    weff_kernel<<<64, 256>>>(fusion_w, out_w, out_b, fusion_b, gamma);
    afull_kernel<<<NB * NC, 2 * NC>>>(fusion_w);

    dim3 mgrid(NPIX / 128, NC / 128, NB);
    main_gemm<<<mgrid, 256>>>(y);
}

// round 13
// speedup vs baseline: 4.1894x; 1.0136x over previous
#include <cuda_runtime.h>
#include <cuda_fp16.h>
#include <cstdint>

#define NB 4
#define NC 256
#define NH 128
#define NW 128
#define NPIX 16384
#define NHEADS 8
#define NCH 32
#define NSPLIT 32

// ---------------- scratch (static device memory; no allocations) ----------------
__device__ __half g_qf[NB * NC * NPIX];       // q fp16
__device__ __half g_kf[NB * NC * NPIX];       // k fp16
__device__ __half g_vf[NB * NC * NPIX];       // v fp16
__device__ __half g_xf[NB * NC * NPIX];       // x fp16
__device__ float g_partial[NSPLIT * NB * NHEADS * NCH * NCH];
__device__ float g_attn[NB * NHEADS * NCH * NCH];
__device__ float g_weff[NC * NC];
__device__ float g_beff[NC];
__device__ __half g_af[NB * NC * 2 * NC];     // A fp16

// ---------------- helpers ----------------
__device__ __forceinline__ unsigned pack_h2(__half a, __half b) {
    __half2 t; t.x = a; t.y = b;
    return *(unsigned*)&t;
}
__device__ __forceinline__ void mma_f16(float* d, const unsigned* a, const unsigned* b) {
    asm volatile(
        "mma.sync.aligned.m16n8k16.row.col.f32.f16.f16.f32 "
        "{%0,%1,%2,%3}, {%4,%5,%6,%7}, {%8,%9}, {%0,%1,%2,%3};"
        : "+f"(d[0]), "+f"(d[1]), "+f"(d[2]), "+f"(d[3])
        : "r"(a[0]), "r"(a[1]), "r"(a[2]), "r"(a[3]), "r"(b[0]), "r"(b[1]));
}
__device__ __forceinline__ void ldsm4(unsigned& d0, unsigned& d1, unsigned& d2, unsigned& d3,
                                      const void* p) {
    unsigned a = (unsigned)__cvta_generic_to_shared(p);
    asm volatile("ldmatrix.sync.aligned.m8n8.x4.shared.b16 {%0,%1,%2,%3},[%4];"
                 : "=r"(d0), "=r"(d1), "=r"(d2), "=r"(d3) : "r"(a));
}
__device__ __forceinline__ void ldsm4t(unsigned& d0, unsigned& d1, unsigned& d2, unsigned& d3,
                                       const void* p) {
    unsigned a = (unsigned)__cvta_generic_to_shared(p);
    asm volatile("ldmatrix.sync.aligned.m8n8.x4.trans.shared.b16 {%0,%1,%2,%3},[%4];"
                 : "=r"(d0), "=r"(d1), "=r"(d2), "=r"(d3) : "r"(a));
}
__device__ __forceinline__ void cpa16(void* s, const void* g) {
    unsigned sa = (unsigned)__cvta_generic_to_shared(s);
    asm volatile("cp.async.cg.shared.global [%0], [%1], 16;" :: "r"(sa), "l"(g));
}

// ---------------- kernel 1: dwconv 3x3 -> q,k,v,x all fp16 ----------------
__global__ __launch_bounds__(256) void dwconv_qkv(
    const float* __restrict__ x,
    const float* __restrict__ qw, const float* __restrict__ qb,
    const float* __restrict__ kw, const float* __restrict__ kb,
    const float* __restrict__ vw, const float* __restrict__ vb)
{
    int bc = blockIdx.x;
    int c  = bc & (NC - 1);
    const float* xp = x + (size_t)bc * NPIX;

    float wq[9], wk[9], wv[9];
#pragma unroll
    for (int t = 0; t < 9; t++) {
        wq[t] = qw[c * 9 + t];
        wk[t] = kw[c * 9 + t];
        wv[t] = vw[c * 9 + t];
    }
    float bq = qb[c], bk = kb[c], bv = vb[c];

    for (int p = threadIdx.x; p < NPIX / 4; p += 256) {
        int i  = p >> 5;
        int j0 = (p & 31) * 4;
        float l[3][6];
#pragma unroll
        for (int dy = 0; dy < 3; dy++) {
            int ii = i + dy - 1;
            if (ii < 0 || ii >= NH) {
#pragma unroll
                for (int t = 0; t < 6; t++) l[dy][t] = 0.f;
            } else {
                const float* rp = xp + ii * NW;
                l[dy][0] = (j0 > 0) ? __ldg(rp + j0 - 1) : 0.f;
                float4 m = *(const float4*)(rp + j0);
                l[dy][1] = m.x; l[dy][2] = m.y; l[dy][3] = m.z; l[dy][4] = m.w;
                l[dy][5] = (j0 + 4 < NW) ? __ldg(rp + j0 + 4) : 0.f;
            }
        }
        float oq[4], ok[4], ov[4];
#pragma unroll
        for (int e = 0; e < 4; e++) {
            float aq = bq, ak = bk, av = bv;
#pragma unroll
            for (int dy = 0; dy < 3; dy++)
#pragma unroll
                for (int dx = 0; dx < 3; dx++) {
                    float xv = l[dy][e + dx];
                    int t = dy * 3 + dx;
                    aq = fmaf(wq[t], xv, aq);
                    ak = fmaf(wk[t], xv, ak);
                    av = fmaf(wv[t], xv, av);
                }
            oq[e] = aq; ok[e] = ak; ov[e] = av;
        }
        size_t o = (size_t)bc * NPIX + (size_t)p * 4;
        *(uint2*)(g_qf + o) = make_uint2(
            pack_h2(__float2half_rn(oq[0]), __float2half_rn(oq[1])),
            pack_h2(__float2half_rn(oq[2]), __float2half_rn(oq[3])));
        *(uint2*)(g_kf + o) = make_uint2(
            pack_h2(__float2half_rn(ok[0]), __float2half_rn(ok[1])),
            pack_h2(__float2half_rn(ok[2]), __float2half_rn(ok[3])));
        *(uint2*)(g_vf + o) = make_uint2(
            pack_h2(__float2half_rn(ov[0]), __float2half_rn(ov[1])),
            pack_h2(__float2half_rn(ov[2]), __float2half_rn(ov[3])));
        *(uint2*)(g_xf + o) = make_uint2(
            pack_h2(__float2half_rn(l[1][1]), __float2half_rn(l[1][2])),
            pack_h2(__float2half_rn(l[1][3]), __float2half_rn(l[1][4])));
    }
}

// ---------------- kernel 2: tensor-core gram S = Q K^T (fp16 in, fp32 acc) ----------------
#define QP 72   // smem pitch (halves): 144B rows -> conflict-free ldmatrix
__global__ __launch_bounds__(128) void gram_tc()
{
    __shared__ __align__(128) __half qs[2][NCH][QP];
    __shared__ __align__(128) __half ks[2][NCH][QP];

    int bh = blockIdx.x;
    int sp = blockIdx.y;
    int p0 = sp * (NPIX / NSPLIT);
    int tid = threadIdx.x;
    int lane = tid & 31;
    int warp = tid >> 5;

    const __half* qp = g_qf + (size_t)bh * NCH * NPIX;
    const __half* kp = g_kf + (size_t)bh * NCH * NPIX;

    float acc[2][4] = {};

    auto load_tile = [&](int s, int t0) {
#pragma unroll
        for (int r = 0; r < 2; r++) {
            int id = tid + r * 128;
            int ch = id >> 3;
            int pc = id & 7;
            cpa16(&qs[s][ch][pc * 8], qp + (size_t)ch * NPIX + t0 + pc * 8);
            cpa16(&ks[s][ch][pc * 8], kp + (size_t)ch * NPIX + t0 + pc * 8);
        }
        asm volatile("cp.async.commit_group;");
    };

    load_tile(0, p0);

    int lr = lane & 15;
    int lc = (lane >> 4) * 8;
    int brow = warp * 8 + (lane & 7);
    int bcol = (lane >> 3) * 8;

    for (int t = 0; t < 8; t++) {
        int cur = t & 1;
        if (t + 1 < 8) {
            load_tile(cur ^ 1, p0 + (t + 1) * 64);
            asm volatile("cp.async.wait_group 1;");
        } else {
            asm volatile("cp.async.wait_group 0;");
        }
        __syncthreads();

#pragma unroll
        for (int s2 = 0; s2 < 2; s2++) {
            int px = s2 * 32;
            unsigned b4[4];
            ldsm4(b4[0], b4[1], b4[2], b4[3], &ks[cur][brow][px + bcol]);
#pragma unroll
            for (int ks16 = 0; ks16 < 2; ks16++) {
                unsigned a0[4], a1[4];
                ldsm4(a0[0], a0[1], a0[2], a0[3], &qs[cur][lr][px + ks16 * 16 + lc]);
                ldsm4(a1[0], a1[1], a1[2], a1[3], &qs[cur][16 + lr][px + ks16 * 16 + lc]);
                mma_f16(acc[0], a0, b4 + ks16 * 2);
                mma_f16(acc[1], a1, b4 + ks16 * 2);
            }
        }
        __syncthreads();
    }

    float* pp = g_partial + ((size_t)sp * NB * NHEADS + bh) * (NCH * NCH);
    int g = lane >> 2, tt = lane & 3;
#pragma unroll
    for (int mt = 0; mt < 2; mt++) {
        int m = mt * 16 + g;
        int n = warp * 8 + tt * 2;
        pp[m * NCH + n]           = acc[mt][0];
        pp[m * NCH + n + 1]       = acc[mt][1];
        pp[(m + 8) * NCH + n]     = acc[mt][2];
        pp[(m + 8) * NCH + n + 1] = acc[mt][3];
    }
}

// ---------------- kernel 3: parallel reduce + softmax (256 thr / bh) ----------------
__global__ __launch_bounds__(256) void softmax_kernel(const float* __restrict__ temperature)
{
    __shared__ float sv[NCH * NCH];

    int bh = blockIdx.x;
    int h = bh & (NHEADS - 1);
    int tid = threadIdx.x;
    int lane = tid & 31;
    int warp = tid >> 5;

    float4 acc = make_float4(0.f, 0.f, 0.f, 0.f);
#pragma unroll 8
    for (int sp = 0; sp < NSPLIT; sp++) {
        const float* p = g_partial + ((size_t)sp * NB * NHEADS + bh) * (NCH * NCH) + tid * 4;
        float4 v = *(const float4*)p;
        acc.x += v.x; acc.y += v.y; acc.z += v.z; acc.w += v.w;
    }
    *(float4*)&sv[tid * 4] = acc;
    __syncthreads();

    float t = temperature[h];
#pragma unroll
    for (int r = 0; r < 4; r++) {
        int row = warp * 4 + r;
        float v = sv[row * NCH + lane] * t;
        float mx = v;
#pragma unroll
        for (int o = 16; o; o >>= 1) mx = fmaxf(mx, __shfl_xor_sync(0xffffffffu, mx, o));
        float e = __expf(v - mx);
        float s = e;
#pragma unroll
        for (int o = 16; o; o >>= 1) s += __shfl_xor_sync(0xffffffffu, s, o);
        g_attn[(size_t)bh * (NCH * NCH) + row * NCH + lane] = e / s;
    }
}

// ---------------- kernel P1: W_eff (32x32 tiles, cp.async pipelined) + b_eff ----------------
__global__ __launch_bounds__(256) void weff_kernel(
    const float* __restrict__ fusion_w, const float* __restrict__ out_w,
    const float* __restrict__ out_b, const float* __restrict__ fusion_b,
    const float* __restrict__ gamma)
{
    __shared__ __align__(16) float Fs[2][32][36];   // [stage][f][k]  (natural layout)
    __shared__ __align__(16) float Os[2][32][36];   // [stage][k][c]

    int f0 = (blockIdx.x >> 3) * 32;
    int c0 = (blockIdx.x & 7) * 32;
    int tid = threadIdx.x;
    int tx = tid & 15, ty = tid >> 4;

    auto load_tile = [&](int s, int ko) {
        // Fs: 32 rows x 32 floats = 256 16B-chunks; Os same. 1+1 per thread.
        int row = tid >> 3;
        int kc  = (tid & 7) * 4;
        cpa16(&Fs[s][row][kc], fusion_w + (size_t)(f0 + row) * (2 * NC) + ko + kc);
        cpa16(&Os[s][row][kc], out_w + (size_t)(ko + row) * NC + c0 + kc);
        asm volatile("cp.async.commit_group;");
    };

    load_tile(0, 0);

    // b_eff on the c0==0 column blocks (overlaps with pipeline fill)
    if ((blockIdx.x & 7) == 0 && tid < 32) {
        int f = f0 + tid;
        float sb = 0.f;
        for (int o = 0; o < NC; o++)
            sb = fmaf(fusion_w[f * 2 * NC + o], out_b[o], sb);
        g_beff[f] = gamma[0] * sb + fusion_b[f];
    }

    float acc[2][2] = {};

    for (int it = 0; it < 8; it++) {
        int cur = it & 1;
        if (it + 1 < 8) {
            load_tile(cur ^ 1, (it + 1) * 32);
            asm volatile("cp.async.wait_group 1;");
        } else {
            asm volatile("cp.async.wait_group 0;");
        }
        __syncthreads();
#pragma unroll
        for (int k = 0; k < 32; k++) {
            float fv0 = Fs[cur][ty * 2][k],     fv1 = Fs[cur][ty * 2 + 1][k];
            float ov0 = Os[cur][k][tx * 2],     ov1 = Os[cur][k][tx * 2 + 1];
            acc[0][0] = fmaf(fv0, ov0, acc[0][0]);
            acc[0][1] = fmaf(fv0, ov1, acc[0][1]);
            acc[1][0] = fmaf(fv1, ov0, acc[1][0]);
            acc[1][1] = fmaf(fv1, ov1, acc[1][1]);
        }
        __syncthreads();
    }
    float g = gamma[0];
#pragma unroll
    for (int i = 0; i < 2; i++)
#pragma unroll
        for (int j = 0; j < 2; j++)
            g_weff[(f0 + ty * 2 + i) * NC + c0 + tx * 2 + j] = g * acc[i][j];
}

// ---------------- kernel P2: A_full -> fp16 (smem-staged attn + weff row) ----------------
__global__ __launch_bounds__(512) void afull_kernel(const float* __restrict__ fusion_w)
{
    __shared__ float at[NHEADS * NCH * NCH];  // attn[b]: 8KB... (8*1024 floats = 32KB) -> stage per-head? 
    __shared__ float wr[NC];

    int bf = blockIdx.x;
    int b = bf >> 8, f = bf & 255;
    int col = threadIdx.x;

    // stage attn[b] (8192 floats = 32KB) coalesced: 16 per thread
    const float* ab = g_attn + (size_t)b * NHEADS * NCH * NCH;
#pragma unroll
    for (int r = 0; r < 16; r++)
        at[col + r * 512] = ab[col + r * 512];
    // stage weff row f (256 floats)
    if (col < NC) wr[col] = g_weff[f * NC + col];
    __syncthreads();

    float v;
    if (col < NC) {
        int h = col >> 5, d = col & 31;
        const float* arow = at + (size_t)h * NCH * NCH + d;
        const float* wrow = wr + h * NCH;
        float s = 0.f;
#pragma unroll
        for (int cc = 0; cc < NCH; cc++)
            s = fmaf(wrow[cc], arow[cc * NCH], s);
        v = s;
    } else {
        v = fusion_w[f * 2 * NC + col];
    }
    g_af[(size_t)bf * 2 * NC + col] = __float2half_rn(v);
}

// ---------------- kernel 4: main GEMM — fp16 HMMA, cp.async 2-stage, BK=64 ----------------
#define AP 72     // A smem pitch (halves): 144B rows -> conflict-free ldmatrix
#define BP 136    // B smem pitch (halves): 272B rows -> conflict-free ldmatrix.trans
__global__ __launch_bounds__(256, 2) void main_gemm(float* __restrict__ y)
{
    __shared__ __align__(128) __half As[2][128][AP];
    __shared__ __align__(128) __half Bs[2][64][BP];

    int b  = blockIdx.z;
    int m0 = blockIdx.y * 128;
    int n0 = blockIdx.x * 128;
    int tid  = threadIdx.x;
    int lane = tid & 31;
    int warp = tid >> 5;
    int wm = (warp >> 2) * 64;
    int wn = (warp & 3) * 32;
    int g = lane >> 2;
    int t = lane & 3;

    int lr = lane & 15;
    int lc = (lane >> 4) * 8;

    const __half* gA = g_af + (size_t)(b * NC + m0) * (2 * NC);

    float acc[4][4][4];
#pragma unroll
    for (int i = 0; i < 4; i++)
#pragma unroll
        for (int j = 0; j < 4; j++)
#pragma unroll
            for (int r = 0; r < 4; r++) acc[i][j][r] = 0.f;

    auto load_stage = [&](int s, int it) {
        int k0 = it * 64;
#pragma unroll
        for (int c = 0; c < 4; c++) {
            int id = tid + c * 256;
            int row = id >> 3;
            int kc = (id & 7) * 8;
            cpa16(&As[s][row][kc], gA + (size_t)row * (2 * NC) + k0 + kc);
        }
#pragma unroll
        for (int c = 0; c < 4; c++) {
            int id = tid + c * 256;
            int krow = id >> 4;
            int nc = (id & 15) * 8;
            int grow = k0 + krow;
            const __half* src = (grow < NC)
                ? g_vf + (size_t)(b * NC + grow) * NPIX + n0 + nc
                : g_xf + (size_t)(b * NC + grow - NC) * NPIX + n0 + nc;
            cpa16(&Bs[s][krow][nc], src);
        }
        asm volatile("cp.async.commit_group;");
    };

    load_stage(0, 0);

    const int NIT = (2 * NC) / 64;   // 8
    for (int it = 0; it < NIT; it++) {
        int cur = it & 1;
        if (it + 1 < NIT) {
            load_stage(cur ^ 1, it + 1);
            asm volatile("cp.async.wait_group 1;");
        } else {
            asm volatile("cp.async.wait_group 0;");
        }
        __syncthreads();

#pragma unroll
        for (int ks = 0; ks < 4; ks++) {
            int kof = ks * 16;
            unsigned bh[4][2];
#pragma unroll
            for (int nb = 0; nb < 2; nb++) {
                unsigned d0, d1, d2, d3;
                ldsm4t(d0, d1, d2, d3, &Bs[cur][kof + lr][wn + nb * 16 + lc]);
                bh[nb * 2][0] = d0; bh[nb * 2][1] = d1;
                bh[nb * 2 + 1][0] = d2; bh[nb * 2 + 1][1] = d3;
            }
            unsigned af[4][4];
#pragma unroll
            for (int mf = 0; mf < 4; mf++)
                ldsm4(af[mf][0], af[mf][1], af[mf][2], af[mf][3],
                      &As[cur][wm + mf * 16 + lr][kof + lc]);
#pragma unroll
            for (int nf = 0; nf < 4; nf++)
#pragma unroll
                for (int mf = 0; mf < 4; mf++)
                    mma_f16(acc[mf][nf], af[mf], bh[nf]);
        }
        __syncthreads();
    }

#pragma unroll
    for (int mf = 0; mf < 4; mf++) {
        int m = m0 + wm + mf * 16 + g;
        float be0 = g_beff[m];
        float be1 = g_beff[m + 8];
        float* yr0 = y + (size_t)(b * NC + m) * NPIX + n0 + wn;
        float* yr1 = yr0 + (size_t)8 * NPIX;
#pragma unroll
        for (int nf = 0; nf < 4; nf++) {
            *(float2*)(yr0 + nf * 8 + t * 2) =
                make_float2(acc[mf][nf][0] + be0, acc[mf][nf][1] + be0);
            *(float2*)(yr1 + nf * 8 + t * 2) =
                make_float2(acc[mf][nf][2] + be1, acc[mf][nf][3] + be1);
        }
    }
}

// ---------------- launch ----------------
extern "C" void kernel_launch(void* const* d_in, const int* in_sizes, int n_in,
                              void* d_out, int out_size)
{
    const float* x        = (const float*)d_in[0];
    const float* q_w      = (const float*)d_in[1];
    const float* q_b      = (const float*)d_in[2];
    const float* k_w      = (const float*)d_in[3];
    const float* k_b      = (const float*)d_in[4];
    const float* v_w      = (const float*)d_in[5];
    const float* v_b      = (const float*)d_in[6];
    const float* out_w    = (const float*)d_in[7];
    const float* out_b    = (const float*)d_in[8];
    const float* fusion_w = (const float*)d_in[9];
    const float* fusion_b = (const float*)d_in[10];
    const float* temperature = (const float*)d_in[11];
    const float* gamma    = (const float*)d_in[12];
    float* y = (float*)d_out;

    dwconv_qkv<<<NB * NC, 256>>>(x, q_w, q_b, k_w, k_b, v_w, v_b);

    dim3 ggrid(NB * NHEADS, NSPLIT);
    gram_tc<<<ggrid, 128>>>();

    softmax_kernel<<<NB * NHEADS, 256>>>(temperature);

    weff_kernel<<<64, 256>>>(fusion_w, out_w, out_b, fusion_b, gamma);
    afull_kernel<<<NB * NC, 2 * NC>>>(fusion_w);

    dim3 mgrid(NPIX / 128, NC / 128, NB);
    main_gemm<<<mgrid, 256>>>(y);
}

// round 14
// speedup vs baseline: 4.4279x; 1.0569x over previous
#include <cuda_runtime.h>
#include <cuda_fp16.h>
#include <cstdint>

#define NB 4
#define NC 256
#define NH 128
#define NW 128
#define NPIX 16384
#define NHEADS 8
#define NCH 32
#define NSPLIT 32

// ---------------- scratch (static device memory; no allocations) ----------------
__device__ __half g_qf[NB * NC * NPIX];       // q fp16
__device__ __half g_kf[NB * NC * NPIX];       // k fp16
__device__ __half g_vf[NB * NC * NPIX];       // v fp16
__device__ __half g_xf[NB * NC * NPIX];       // x fp16
__device__ float g_partial[NSPLIT * NB * NHEADS * NCH * NCH];
__device__ float g_attn[NB * NHEADS * NCH * NCH];
__device__ float g_weff[NC * NC];
__device__ float g_beff[NC];
__device__ __half g_af[NB * NC * 2 * NC];     // A fp16

// ---------------- helpers ----------------
__device__ __forceinline__ unsigned pack_h2(__half a, __half b) {
    __half2 t; t.x = a; t.y = b;
    return *(unsigned*)&t;
}
__device__ __forceinline__ void mma_f16(float* d, const unsigned* a, const unsigned* b) {
    asm volatile(
        "mma.sync.aligned.m16n8k16.row.col.f32.f16.f16.f32 "
        "{%0,%1,%2,%3}, {%4,%5,%6,%7}, {%8,%9}, {%0,%1,%2,%3};"
        : "+f"(d[0]), "+f"(d[1]), "+f"(d[2]), "+f"(d[3])
        : "r"(a[0]), "r"(a[1]), "r"(a[2]), "r"(a[3]), "r"(b[0]), "r"(b[1]));
}
__device__ __forceinline__ void ldsm4(unsigned& d0, unsigned& d1, unsigned& d2, unsigned& d3,
                                      const void* p) {
    unsigned a = (unsigned)__cvta_generic_to_shared(p);
    asm volatile("ldmatrix.sync.aligned.m8n8.x4.shared.b16 {%0,%1,%2,%3},[%4];"
                 : "=r"(d0), "=r"(d1), "=r"(d2), "=r"(d3) : "r"(a));
}
__device__ __forceinline__ void ldsm4t(unsigned& d0, unsigned& d1, unsigned& d2, unsigned& d3,
                                       const void* p) {
    unsigned a = (unsigned)__cvta_generic_to_shared(p);
    asm volatile("ldmatrix.sync.aligned.m8n8.x4.trans.shared.b16 {%0,%1,%2,%3},[%4];"
                 : "=r"(d0), "=r"(d1), "=r"(d2), "=r"(d3) : "r"(a));
}
__device__ __forceinline__ void cpa16(void* s, const void* g) {
    unsigned sa = (unsigned)__cvta_generic_to_shared(s);
    asm volatile("cp.async.cg.shared.global [%0], [%1], 16;" :: "r"(sa), "l"(g));
}

// ---------------- kernel 1: dwconv 3x3 -> q,k,v,x all fp16 ----------------
__global__ __launch_bounds__(256) void dwconv_qkv(
    const float* __restrict__ x,
    const float* __restrict__ qw, const float* __restrict__ qb,
    const float* __restrict__ kw, const float* __restrict__ kb,
    const float* __restrict__ vw, const float* __restrict__ vb)
{
    int bc = blockIdx.x;
    int c  = bc & (NC - 1);
    const float* xp = x + (size_t)bc * NPIX;

    float wq[9], wk[9], wv[9];
#pragma unroll
    for (int t = 0; t < 9; t++) {
        wq[t] = qw[c * 9 + t];
        wk[t] = kw[c * 9 + t];
        wv[t] = vw[c * 9 + t];
    }
    float bq = qb[c], bk = kb[c], bv = vb[c];

    for (int p = threadIdx.x; p < NPIX / 4; p += 256) {
        int i  = p >> 5;
        int j0 = (p & 31) * 4;
        float l[3][6];
#pragma unroll
        for (int dy = 0; dy < 3; dy++) {
            int ii = i + dy - 1;
            if (ii < 0 || ii >= NH) {
#pragma unroll
                for (int t = 0; t < 6; t++) l[dy][t] = 0.f;
            } else {
                const float* rp = xp + ii * NW;
                l[dy][0] = (j0 > 0) ? __ldg(rp + j0 - 1) : 0.f;
                float4 m = *(const float4*)(rp + j0);
                l[dy][1] = m.x; l[dy][2] = m.y; l[dy][3] = m.z; l[dy][4] = m.w;
                l[dy][5] = (j0 + 4 < NW) ? __ldg(rp + j0 + 4) : 0.f;
            }
        }
        float oq[4], ok[4], ov[4];
#pragma unroll
        for (int e = 0; e < 4; e++) {
            float aq = bq, ak = bk, av = bv;
#pragma unroll
            for (int dy = 0; dy < 3; dy++)
#pragma unroll
                for (int dx = 0; dx < 3; dx++) {
                    float xv = l[dy][e + dx];
                    int t = dy * 3 + dx;
                    aq = fmaf(wq[t], xv, aq);
                    ak = fmaf(wk[t], xv, ak);
                    av = fmaf(wv[t], xv, av);
                }
            oq[e] = aq; ok[e] = ak; ov[e] = av;
        }
        size_t o = (size_t)bc * NPIX + (size_t)p * 4;
        *(uint2*)(g_qf + o) = make_uint2(
            pack_h2(__float2half_rn(oq[0]), __float2half_rn(oq[1])),
            pack_h2(__float2half_rn(oq[2]), __float2half_rn(oq[3])));
        *(uint2*)(g_kf + o) = make_uint2(
            pack_h2(__float2half_rn(ok[0]), __float2half_rn(ok[1])),
            pack_h2(__float2half_rn(ok[2]), __float2half_rn(ok[3])));
        *(uint2*)(g_vf + o) = make_uint2(
            pack_h2(__float2half_rn(ov[0]), __float2half_rn(ov[1])),
            pack_h2(__float2half_rn(ov[2]), __float2half_rn(ov[3])));
        *(uint2*)(g_xf + o) = make_uint2(
            pack_h2(__float2half_rn(l[1][1]), __float2half_rn(l[1][2])),
            pack_h2(__float2half_rn(l[1][3]), __float2half_rn(l[1][4])));
    }
}

// ---------------- kernel 2: tensor-core gram S = Q K^T (fp16 in, fp32 acc) ----------------
#define QP 72   // smem pitch (halves): 144B rows -> conflict-free ldmatrix
__global__ __launch_bounds__(128) void gram_tc()
{
    __shared__ __align__(128) __half qs[2][NCH][QP];
    __shared__ __align__(128) __half ks[2][NCH][QP];

    int bh = blockIdx.x;
    int sp = blockIdx.y;
    int p0 = sp * (NPIX / NSPLIT);
    int tid = threadIdx.x;
    int lane = tid & 31;
    int warp = tid >> 5;

    const __half* qp = g_qf + (size_t)bh * NCH * NPIX;
    const __half* kp = g_kf + (size_t)bh * NCH * NPIX;

    float acc[2][4] = {};

    auto load_tile = [&](int s, int t0) {
#pragma unroll
        for (int r = 0; r < 2; r++) {
            int id = tid + r * 128;
            int ch = id >> 3;
            int pc = id & 7;
            cpa16(&qs[s][ch][pc * 8], qp + (size_t)ch * NPIX + t0 + pc * 8);
            cpa16(&ks[s][ch][pc * 8], kp + (size_t)ch * NPIX + t0 + pc * 8);
        }
        asm volatile("cp.async.commit_group;");
    };

    load_tile(0, p0);

    int lr = lane & 15;
    int lc = (lane >> 4) * 8;
    int brow = warp * 8 + (lane & 7);
    int bcol = (lane >> 3) * 8;

    for (int t = 0; t < 8; t++) {
        int cur = t & 1;
        if (t + 1 < 8) {
            load_tile(cur ^ 1, p0 + (t + 1) * 64);
            asm volatile("cp.async.wait_group 1;");
        } else {
            asm volatile("cp.async.wait_group 0;");
        }
        __syncthreads();

#pragma unroll
        for (int s2 = 0; s2 < 2; s2++) {
            int px = s2 * 32;
            unsigned b4[4];
            ldsm4(b4[0], b4[1], b4[2], b4[3], &ks[cur][brow][px + bcol]);
#pragma unroll
            for (int ks16 = 0; ks16 < 2; ks16++) {
                unsigned a0[4], a1[4];
                ldsm4(a0[0], a0[1], a0[2], a0[3], &qs[cur][lr][px + ks16 * 16 + lc]);
                ldsm4(a1[0], a1[1], a1[2], a1[3], &qs[cur][16 + lr][px + ks16 * 16 + lc]);
                mma_f16(acc[0], a0, b4 + ks16 * 2);
                mma_f16(acc[1], a1, b4 + ks16 * 2);
            }
        }
        __syncthreads();
    }

    float* pp = g_partial + ((size_t)sp * NB * NHEADS + bh) * (NCH * NCH);
    int g = lane >> 2, tt = lane & 3;
#pragma unroll
    for (int mt = 0; mt < 2; mt++) {
        int m = mt * 16 + g;
        int n = warp * 8 + tt * 2;
        pp[m * NCH + n]           = acc[mt][0];
        pp[m * NCH + n + 1]       = acc[mt][1];
        pp[(m + 8) * NCH + n]     = acc[mt][2];
        pp[(m + 8) * NCH + n + 1] = acc[mt][3];
    }
}

// ---------------- kernel 3: parallel reduce + softmax (256 thr / bh) ----------------
__global__ __launch_bounds__(256) void softmax_kernel(const float* __restrict__ temperature)
{
    __shared__ float sv[NCH * NCH];

    int bh = blockIdx.x;
    int h = bh & (NHEADS - 1);
    int tid = threadIdx.x;
    int lane = tid & 31;
    int warp = tid >> 5;

    float4 acc = make_float4(0.f, 0.f, 0.f, 0.f);
#pragma unroll 8
    for (int sp = 0; sp < NSPLIT; sp++) {
        const float* p = g_partial + ((size_t)sp * NB * NHEADS + bh) * (NCH * NCH) + tid * 4;
        float4 v = *(const float4*)p;
        acc.x += v.x; acc.y += v.y; acc.z += v.z; acc.w += v.w;
    }
    *(float4*)&sv[tid * 4] = acc;
    __syncthreads();

    float t = temperature[h];
#pragma unroll
    for (int r = 0; r < 4; r++) {
        int row = warp * 4 + r;
        float v = sv[row * NCH + lane] * t;
        float mx = v;
#pragma unroll
        for (int o = 16; o; o >>= 1) mx = fmaxf(mx, __shfl_xor_sync(0xffffffffu, mx, o));
        float e = __expf(v - mx);
        float s = e;
#pragma unroll
        for (int o = 16; o; o >>= 1) s += __shfl_xor_sync(0xffffffffu, s, o);
        g_attn[(size_t)bh * (NCH * NCH) + row * NCH + lane] = e / s;
    }
}

// ---------------- kernel P0: b_eff (warp-reduce, grid 256) ----------------
__global__ __launch_bounds__(32) void beff_kernel(
    const float* __restrict__ fusion_w, const float* __restrict__ out_b,
    const float* __restrict__ fusion_b, const float* __restrict__ gamma)
{
    int f = blockIdx.x;
    int l = threadIdx.x;
    float s = 0.f;
#pragma unroll
    for (int o = l; o < NC; o += 32)
        s = fmaf(fusion_w[f * 2 * NC + o], out_b[o], s);
#pragma unroll
    for (int off = 16; off; off >>= 1)
        s += __shfl_down_sync(0xffffffffu, s, off);
    if (l == 0) g_beff[f] = gamma[0] * s + fusion_b[f];
}

// ---------------- kernel P1: W_eff (32x32 tiles, cp.async pipelined) ----------------
__global__ __launch_bounds__(256) void weff_kernel(
    const float* __restrict__ fusion_w, const float* __restrict__ out_w,
    const float* __restrict__ gamma)
{
    __shared__ __align__(16) float Fs[2][32][36];   // [stage][f][k]
    __shared__ __align__(16) float Os[2][32][36];   // [stage][k][c]

    int f0 = (blockIdx.x >> 3) * 32;
    int c0 = (blockIdx.x & 7) * 32;
    int tid = threadIdx.x;
    int tx = tid & 15, ty = tid >> 4;

    auto load_tile = [&](int s, int ko) {
        int row = tid >> 3;
        int kc  = (tid & 7) * 4;
        cpa16(&Fs[s][row][kc], fusion_w + (size_t)(f0 + row) * (2 * NC) + ko + kc);
        cpa16(&Os[s][row][kc], out_w + (size_t)(ko + row) * NC + c0 + kc);
        asm volatile("cp.async.commit_group;");
    };

    load_tile(0, 0);

    float acc[2][2] = {};

    for (int it = 0; it < 8; it++) {
        int cur = it & 1;
        if (it + 1 < 8) {
            load_tile(cur ^ 1, (it + 1) * 32);
            asm volatile("cp.async.wait_group 1;");
        } else {
            asm volatile("cp.async.wait_group 0;");
        }
        __syncthreads();
#pragma unroll
        for (int k = 0; k < 32; k++) {
            float fv0 = Fs[cur][ty * 2][k],     fv1 = Fs[cur][ty * 2 + 1][k];
            float ov0 = Os[cur][k][tx * 2],     ov1 = Os[cur][k][tx * 2 + 1];
            acc[0][0] = fmaf(fv0, ov0, acc[0][0]);
            acc[0][1] = fmaf(fv0, ov1, acc[0][1]);
            acc[1][0] = fmaf(fv1, ov0, acc[1][0]);
            acc[1][1] = fmaf(fv1, ov1, acc[1][1]);
        }
        __syncthreads();
    }
    float g = gamma[0];
#pragma unroll
    for (int i = 0; i < 2; i++)
#pragma unroll
        for (int j = 0; j < 2; j++)
            g_weff[(f0 + ty * 2 + i) * NC + c0 + tx * 2 + j] = g * acc[i][j];
}

// ---------------- kernel P2: A_full -> fp16 (smem-staged attn + weff row) ----------------
__global__ __launch_bounds__(512) void afull_kernel(const float* __restrict__ fusion_w)
{
    __shared__ float at[NHEADS * NCH * NCH];
    __shared__ float wr[NC];

    int bf = blockIdx.x;
    int b = bf >> 8, f = bf & 255;
    int col = threadIdx.x;

    const float* ab = g_attn + (size_t)b * NHEADS * NCH * NCH;
#pragma unroll
    for (int r = 0; r < 16; r++)
        at[col + r * 512] = ab[col + r * 512];
    if (col < NC) wr[col] = g_weff[f * NC + col];
    __syncthreads();

    float v;
    if (col < NC) {
        int h = col >> 5, d = col & 31;
        const float* arow = at + (size_t)h * NCH * NCH + d;
        const float* wrow = wr + h * NCH;
        float s = 0.f;
#pragma unroll
        for (int cc = 0; cc < NCH; cc++)
            s = fmaf(wrow[cc], arow[cc * NCH], s);
        v = s;
    } else {
        v = fusion_w[f * 2 * NC + col];
    }
    g_af[(size_t)bf * 2 * NC + col] = __float2half_rn(v);
}

// ---------------- kernel 4: main GEMM — fp16 HMMA, cp.async 2-stage, BK=64 ----------------
#define AP 72     // A smem pitch (halves): 144B rows -> conflict-free ldmatrix
#define BP 136    // B smem pitch (halves): 272B rows -> conflict-free ldmatrix.trans
__global__ __launch_bounds__(256, 2) void main_gemm(float* __restrict__ y)
{
    __shared__ __align__(128) __half As[2][128][AP];
    __shared__ __align__(128) __half Bs[2][64][BP];

    int b  = blockIdx.z;
    int m0 = blockIdx.y * 128;
    int n0 = blockIdx.x * 128;
    int tid  = threadIdx.x;
    int lane = tid & 31;
    int warp = tid >> 5;
    int wm = (warp >> 2) * 64;
    int wn = (warp & 3) * 32;
    int g = lane >> 2;
    int t = lane & 3;

    int lr = lane & 15;
    int lc = (lane >> 4) * 8;

    const __half* gA = g_af + (size_t)(b * NC + m0) * (2 * NC);

    float acc[4][4][4];
#pragma unroll
    for (int i = 0; i < 4; i++)
#pragma unroll
        for (int j = 0; j < 4; j++)
#pragma unroll
            for (int r = 0; r < 4; r++) acc[i][j][r] = 0.f;

    auto load_stage = [&](int s, int it) {
        int k0 = it * 64;
#pragma unroll
        for (int c = 0; c < 4; c++) {
            int id = tid + c * 256;
            int row = id >> 3;
            int kc = (id & 7) * 8;
            cpa16(&As[s][row][kc], gA + (size_t)row * (2 * NC) + k0 + kc);
        }
#pragma unroll
        for (int c = 0; c < 4; c++) {
            int id = tid + c * 256;
            int krow = id >> 4;
            int nc = (id & 15) * 8;
            int grow = k0 + krow;
            const __half* src = (grow < NC)
                ? g_vf + (size_t)(b * NC + grow) * NPIX + n0 + nc
                : g_xf + (size_t)(b * NC + grow - NC) * NPIX + n0 + nc;
            cpa16(&Bs[s][krow][nc], src);
        }
        asm volatile("cp.async.commit_group;");
    };

    load_stage(0, 0);

    const int NIT = (2 * NC) / 64;   // 8
    for (int it = 0; it < NIT; it++) {
        int cur = it & 1;
        if (it + 1 < NIT) {
            load_stage(cur ^ 1, it + 1);
            asm volatile("cp.async.wait_group 1;");
        } else {
            asm volatile("cp.async.wait_group 0;");
        }
        __syncthreads();

#pragma unroll
        for (int ks = 0; ks < 4; ks++) {
            int kof = ks * 16;
            unsigned bh[4][2];
#pragma unroll
            for (int nb = 0; nb < 2; nb++) {
                unsigned d0, d1, d2, d3;
                ldsm4t(d0, d1, d2, d3, &Bs[cur][kof + lr][wn + nb * 16 + lc]);
                bh[nb * 2][0] = d0; bh[nb * 2][1] = d1;
                bh[nb * 2 + 1][0] = d2; bh[nb * 2 + 1][1] = d3;
            }
            unsigned af[4][4];
#pragma unroll
            for (int mf = 0; mf < 4; mf++)
                ldsm4(af[mf][0], af[mf][1], af[mf][2], af[mf][3],
                      &As[cur][wm + mf * 16 + lr][kof + lc]);
#pragma unroll
            for (int nf = 0; nf < 4; nf++)
#pragma unroll
                for (int mf = 0; mf < 4; mf++)
                    mma_f16(acc[mf][nf], af[mf], bh[nf]);
        }
        __syncthreads();
    }

#pragma unroll
    for (int mf = 0; mf < 4; mf++) {
        int m = m0 + wm + mf * 16 + g;
        float be0 = g_beff[m];
        float be1 = g_beff[m + 8];
        float* yr0 = y + (size_t)(b * NC + m) * NPIX + n0 + wn;
        float* yr1 = yr0 + (size_t)8 * NPIX;
#pragma unroll
        for (int nf = 0; nf < 4; nf++) {
            *(float2*)(yr0 + nf * 8 + t * 2) =
                make_float2(acc[mf][nf][0] + be0, acc[mf][nf][1] + be0);
            *(float2*)(yr1 + nf * 8 + t * 2) =
                make_float2(acc[mf][nf][2] + be1, acc[mf][nf][3] + be1);
        }
    }
}

// ---------------- launch ----------------
extern "C" void kernel_launch(void* const* d_in, const int* in_sizes, int n_in,
                              void* d_out, int out_size)
{
    const float* x        = (const float*)d_in[0];
    const float* q_w      = (const float*)d_in[1];
    const float* q_b      = (const float*)d_in[2];
    const float* k_w      = (const float*)d_in[3];
    const float* k_b      = (const float*)d_in[4];
    const float* v_w      = (const float*)d_in[5];
    const float* v_b      = (const float*)d_in[6];
    const float* out_w    = (const float*)d_in[7];
    const float* out_b    = (const float*)d_in[8];
    const float* fusion_w = (const float*)d_in[9];
    const float* fusion_b = (const float*)d_in[10];
    const float* temperature = (const float*)d_in[11];
    const float* gamma    = (const float*)d_in[12];
    float* y = (float*)d_out;

    dwconv_qkv<<<NB * NC, 256>>>(x, q_w, q_b, k_w, k_b, v_w, v_b);

    dim3 ggrid(NB * NHEADS, NSPLIT);
    gram_tc<<<ggrid, 128>>>();

    softmax_kernel<<<NB * NHEADS, 256>>>(temperature);

    beff_kernel<<<NC, 32>>>(fusion_w, out_b, fusion_b, gamma);
    weff_kernel<<<64, 256>>>(fusion_w, out_w, gamma);
    afull_kernel<<<NB * NC, 2 * NC>>>(fusion_w);

    dim3 mgrid(NPIX / 128, NC / 128, NB);
    main_gemm<<<mgrid, 256>>>(y);
}